// round 2
// baseline (speedup 1.0000x reference)
#include <cuda_runtime.h>
#include <cuda_bf16.h>
#include <math.h>

#define N_NODES 32768
#define EMB 512
#define HEADS 4
#define OUT 2048      // EMB*HEADS
#define NE 131072     // directed edges
#define NTOT (NE + N_NODES)  // with self loops
#define NB 32         // graphs
#define HID 32

// ---------------- scratch (static device globals; no allocs allowed) -------
__device__ float    d_x[(size_t)N_NODES * EMB];        // after feat linear
__device__ float    d_h[(size_t)N_NODES * OUT];        // after W_gat
__device__ float    d_of[(size_t)N_NODES * OUT];       // GAT output (post act)
__device__ float    d_asrc[N_NODES * HEADS];
__device__ float    d_adst[N_NODES * HEADS];
__device__ float    d_alpha[(size_t)NTOT * HEADS];
__device__ unsigned d_amax[N_NODES * HEADS];
__device__ float    d_denom[N_NODES * HEADS];
__device__ int      d_deg[N_NODES];
__device__ int      d_off[N_NODES + 1];
__device__ int      d_pos[N_NODES];
__device__ int      d_eidx[NTOT];
__device__ float    d_g[NB * 2 * OUT];
__device__ int      d_gstart[NB + 1];

// monotonic float<->uint encoding for atomicMax on signed floats
__device__ __forceinline__ unsigned fenc(float f) {
    unsigned u = __float_as_uint(f);
    return (u >> 31) ? ~u : (u | 0x80000000u);
}
__device__ __forceinline__ float fdec(unsigned u) {
    u = (u >> 31) ? (u & 0x7fffffffu) : ~u;
    return __uint_as_float(u);
}

// ---------------- init ------------------------------------------------------
__global__ void init_kernel() {
    int i = blockIdx.x * blockDim.x + threadIdx.x;
    if (i < N_NODES * HEADS) { d_amax[i] = 0u; d_denom[i] = 0.f; }
    if (i < N_NODES) d_deg[i] = 0;
    if (i <= NB) d_gstart[i] = N_NODES;
}

// ---------------- generic tiled fp32 GEMM: C = gather(A) @ W (+bias) --------
// 64x64 tile, BK=16, 256 threads, 4x4 per-thread. M,Ncols,K all multiples.
__global__ void gemm_kernel(const float* __restrict__ A,
                            const int* __restrict__ gather,
                            const float* __restrict__ Wm,
                            const float* __restrict__ bias,
                            float* __restrict__ C,
                            int K, int Ncols) {
    __shared__ float As[16][64];
    __shared__ float Bs[16][64];
    int tid = threadIdx.x;
    int brow = blockIdx.y * 64, bcol = blockIdx.x * 64;
    int arow = tid >> 2, acol0 = (tid & 3) * 4;
    int bkrow = tid >> 4, bcol0 = (tid & 15) * 4;
    int ty = tid >> 4, tx = tid & 15;

    const float* aptr;
    {
        int grow = brow + arow;
        long row = gather ? (long)gather[grow] : (long)grow;
        aptr = A + row * (long)K;
    }

    float acc[4][4];
#pragma unroll
    for (int i = 0; i < 4; i++)
#pragma unroll
        for (int j = 0; j < 4; j++) acc[i][j] = 0.f;

    for (int kk = 0; kk < K; kk += 16) {
        float4 av = *(const float4*)(aptr + kk + acol0);
        As[acol0 + 0][arow] = av.x;
        As[acol0 + 1][arow] = av.y;
        As[acol0 + 2][arow] = av.z;
        As[acol0 + 3][arow] = av.w;
        float4 bv = *(const float4*)(Wm + (long)(kk + bkrow) * Ncols + bcol + bcol0);
        *(float4*)&Bs[bkrow][bcol0] = bv;
        __syncthreads();
#pragma unroll
        for (int k = 0; k < 16; k++) {
            float4 a = *(const float4*)&As[k][ty * 4];
            float4 b = *(const float4*)&Bs[k][tx * 4];
            acc[0][0] += a.x * b.x; acc[0][1] += a.x * b.y; acc[0][2] += a.x * b.z; acc[0][3] += a.x * b.w;
            acc[1][0] += a.y * b.x; acc[1][1] += a.y * b.y; acc[1][2] += a.y * b.z; acc[1][3] += a.y * b.w;
            acc[2][0] += a.z * b.x; acc[2][1] += a.z * b.y; acc[2][2] += a.z * b.z; acc[2][3] += a.z * b.w;
            acc[3][0] += a.w * b.x; acc[3][1] += a.w * b.y; acc[3][2] += a.w * b.z; acc[3][3] += a.w * b.w;
        }
        __syncthreads();
    }

    int row0 = brow + ty * 4, col0 = bcol + tx * 4;
    float bb[4] = {0.f, 0.f, 0.f, 0.f};
    if (bias) {
        float4 b4 = *(const float4*)(bias + col0);
        bb[0] = b4.x; bb[1] = b4.y; bb[2] = b4.z; bb[3] = b4.w;
    }
#pragma unroll
    for (int i = 0; i < 4; i++) {
        float4 o;
        o.x = acc[i][0] + bb[0];
        o.y = acc[i][1] + bb[1];
        o.z = acc[i][2] + bb[2];
        o.w = acc[i][3] + bb[3];
        *(float4*)(C + (long)(row0 + i) * Ncols + col0) = o;
    }
}

// ---------------- per-node attention scalars --------------------------------
__global__ void attn_kernel(const float* __restrict__ att_src,
                            const float* __restrict__ att_dst) {
    int n = blockIdx.x;
    int w = threadIdx.x >> 5, lane = threadIdx.x & 31;
    const float* hr = d_h + (size_t)n * OUT + w * EMB;
    const float* as = att_src + w * EMB;
    const float* ad = att_dst + w * EMB;
    float s1 = 0.f, s2 = 0.f;
    for (int c = lane; c < EMB; c += 32) {
        float v = hr[c];
        s1 += v * as[c];
        s2 += v * ad[c];
    }
#pragma unroll
    for (int o = 16; o; o >>= 1) {
        s1 += __shfl_down_sync(0xffffffffu, s1, o);
        s2 += __shfl_down_sync(0xffffffffu, s2, o);
    }
    if (lane == 0) { d_asrc[n * 4 + w] = s1; d_adst[n * 4 + w] = s2; }
}

// ---------------- CSR build -------------------------------------------------
__global__ void count_kernel(const int* __restrict__ ei) {
    int e = blockIdx.x * blockDim.x + threadIdx.x;
    if (e >= NTOT) return;
    int dst = (e < NE) ? ei[NE + e] : (e - NE);
    atomicAdd(&d_deg[dst], 1);
}

__global__ void scan_kernel() {  // 1 block, 1024 threads
    __shared__ int sh[1024];
    __shared__ int carry;
    int tid = threadIdx.x;
    if (tid == 0) carry = 0;
    __syncthreads();
    for (int ch = 0; ch < N_NODES / 1024; ch++) {
        int i = ch * 1024 + tid;
        int v = d_deg[i];
        sh[tid] = v;
        __syncthreads();
        for (int o = 1; o < 1024; o <<= 1) {
            int x = (tid >= o) ? sh[tid - o] : 0;
            __syncthreads();
            sh[tid] += x;
            __syncthreads();
        }
        int excl = carry + sh[tid] - v;
        d_off[i] = excl;
        d_pos[i] = excl;
        __syncthreads();
        if (tid == 1023) carry += sh[1023];
        __syncthreads();
    }
    if (tid == 0) d_off[N_NODES] = carry;
}

__global__ void scatter_kernel(const int* __restrict__ ei) {
    int e = blockIdx.x * blockDim.x + threadIdx.x;
    if (e >= NTOT) return;
    int dst = (e < NE) ? ei[NE + e] : (e - NE);
    int p = atomicAdd(&d_pos[dst], 1);
    d_eidx[p] = e;
}

// ---------------- softmax passes -------------------------------------------
__global__ void alpha1_kernel(const int* __restrict__ ei) {
    int e = blockIdx.x * blockDim.x + threadIdx.x;
    if (e >= NTOT) return;
    int src, dst;
    if (e < NE) { src = ei[e]; dst = ei[NE + e]; }
    else        { src = dst = e - NE; }
    float4 as = *(const float4*)&d_asrc[src * 4];
    float4 ad = *(const float4*)&d_adst[dst * 4];
    float r[4] = {as.x + ad.x, as.y + ad.y, as.z + ad.z, as.w + ad.w};
#pragma unroll
    for (int h = 0; h < 4; h++) {
        r[h] = r[h] > 0.f ? r[h] : 0.2f * r[h];
        atomicMax(&d_amax[dst * 4 + h], fenc(r[h]));
    }
    *(float4*)&d_alpha[(size_t)e * 4] = make_float4(r[0], r[1], r[2], r[3]);
}

__global__ void alpha2_kernel(const int* __restrict__ ei) {
    int e = blockIdx.x * blockDim.x + threadIdx.x;
    if (e >= NTOT) return;
    int dst = (e < NE) ? ei[NE + e] : (e - NE);
    float4 r = *(const float4*)&d_alpha[(size_t)e * 4];
    float a0 = expf(r.x - fdec(d_amax[dst * 4 + 0]));
    float a1 = expf(r.y - fdec(d_amax[dst * 4 + 1]));
    float a2 = expf(r.z - fdec(d_amax[dst * 4 + 2]));
    float a3 = expf(r.w - fdec(d_amax[dst * 4 + 3]));
    *(float4*)&d_alpha[(size_t)e * 4] = make_float4(a0, a1, a2, a3);
    atomicAdd(&d_denom[dst * 4 + 0], a0);
    atomicAdd(&d_denom[dst * 4 + 1], a1);
    atomicAdd(&d_denom[dst * 4 + 2], a2);
    atomicAdd(&d_denom[dst * 4 + 3], a3);
}

// ---------------- message aggregation (CSR, no atomics) ---------------------
__global__ void aggregate_kernel(const int* __restrict__ ei,
                                 const float* __restrict__ bias_gat) {
    int dst = blockIdx.x, t = threadIdx.x;  // 256 threads
    float acc[8] = {0.f, 0.f, 0.f, 0.f, 0.f, 0.f, 0.f, 0.f};
    int s = d_off[dst], e = d_off[dst + 1];
    float4 dn = *(const float4*)&d_denom[dst * 4];
    float inv0 = 1.f / (dn.x + 1e-16f);
    float inv1 = 1.f / (dn.y + 1e-16f);
    float inv2 = 1.f / (dn.z + 1e-16f);
    float inv3 = 1.f / (dn.w + 1e-16f);
    for (int i = s; i < e; i++) {
        int ed = d_eidx[i];
        int src = (ed < NE) ? ei[ed] : (ed - NE);
        float4 al = *(const float4*)&d_alpha[(size_t)ed * 4];
        float c0 = al.x * inv0, c1 = al.y * inv1, c2 = al.z * inv2, c3 = al.w * inv3;
        const float* hr = d_h + (size_t)src * OUT;
        acc[0] += hr[t +    0] * c0;
        acc[1] += hr[t +  256] * c0;
        acc[2] += hr[t +  512] * c1;
        acc[3] += hr[t +  768] * c1;
        acc[4] += hr[t + 1024] * c2;
        acc[5] += hr[t + 1280] * c2;
        acc[6] += hr[t + 1536] * c3;
        acc[7] += hr[t + 1792] * c3;
    }
#pragma unroll
    for (int j = 0; j < 8; j++) {
        int c = t + 256 * j;
        float v = acc[j] + bias_gat[c];
        v = v > 0.f ? v : 0.01f * v;   // outer leaky_relu (default slope 0.01)
        d_of[(size_t)dst * OUT + c] = v;
    }
}

// ---------------- graph boundaries + pooling --------------------------------
__global__ void gbound_kernel(const int* __restrict__ batch) {
    int i = blockIdx.x * blockDim.x + threadIdx.x;
    if (i >= N_NODES) return;
    atomicMin(&d_gstart[batch[i]], i);
}

__global__ void gfix_kernel() {
    if (threadIdx.x == 0) {
        d_gstart[NB] = N_NODES;
        for (int b = NB - 1; b >= 0; b--)
            if (d_gstart[b] > d_gstart[b + 1]) d_gstart[b] = d_gstart[b + 1];
    }
}

__global__ void pool_kernel() {  // grid (16, NB), 128 threads
    int b = blockIdx.y;
    int c = blockIdx.x * 128 + threadIdx.x;
    int s = d_gstart[b], e = d_gstart[b + 1];
    float sum = 0.f, mx = -INFINITY;
    for (int i = s; i < e; i++) {
        float v = d_of[(size_t)i * OUT + c];
        sum += v;
        mx = fmaxf(mx, v);
    }
    float cnt = (float)(e - s);
    d_g[b * 2 * OUT + c] = sum / fmaxf(cnt, 1.f);
    d_g[b * 2 * OUT + OUT + c] = mx;
}

// ---------------- head MLPs -------------------------------------------------
__global__ void mlp_kernel(const float* __restrict__ W1r, const float* __restrict__ b1r,
                           const float* __restrict__ W2r, const float* __restrict__ b2r,
                           const float* __restrict__ W1m, const float* __restrict__ b1m,
                           const float* __restrict__ W2m, const float* __restrict__ b2m,
                           float* __restrict__ out) {
    int b = blockIdx.x, task = blockIdx.y;
    const float* W1 = task ? W1m : W1r;
    const float* b1 = task ? b1m : b1r;
    const float* W2 = task ? W2m : W2r;
    const float* b2 = task ? b2m : b2r;
    __shared__ float gs[2 * OUT];
    __shared__ float part[128];
    int t = threadIdx.x;  // 128
    for (int k = t; k < 2 * OUT; k += 128) gs[k] = d_g[b * 2 * OUT + k];
    __syncthreads();
    int j = t & 31, seg = t >> 5;
    float s = 0.f;
    for (int k = seg; k < 2 * OUT; k += 4) s += gs[k] * W1[k * HID + j];
    part[t] = s;
    __syncthreads();
    if (t < 32) {
        float hj = part[t] + part[t + 32] + part[t + 64] + part[t + 96] + b1[t];
        hj = fmaxf(hj, 0.f);
        float p = hj * W2[t];
#pragma unroll
        for (int o = 16; o; o >>= 1) p += __shfl_down_sync(0xffffffffu, p, o);
        if (t == 0) out[task * NB + b] = p + b2[0];
    }
}

// ---------------- launch ----------------------------------------------------
extern "C" void kernel_launch(void* const* d_in, const int* in_sizes, int n_in,
                              void* d_out, int out_size) {
    const int*   code     = (const int*)d_in[0];
    const int*   ei       = (const int*)d_in[1];
    const int*   batch    = (const int*)d_in[2];
    const float* emb      = (const float*)d_in[3];
    const float* W_feat   = (const float*)d_in[4];
    const float* b_feat   = (const float*)d_in[5];
    const float* W_gat    = (const float*)d_in[6];
    const float* att_src  = (const float*)d_in[7];
    const float* att_dst  = (const float*)d_in[8];
    const float* bias_gat = (const float*)d_in[9];
    const float* W1r = (const float*)d_in[10];
    const float* b1r = (const float*)d_in[11];
    const float* W2r = (const float*)d_in[12];
    const float* b2r = (const float*)d_in[13];
    const float* W1m = (const float*)d_in[14];
    const float* b1m = (const float*)d_in[15];
    const float* W2m = (const float*)d_in[16];
    const float* b2m = (const float*)d_in[17];
    float* out = (float*)d_out;

    void *px, *ph;
    cudaGetSymbolAddress(&px, d_x);
    cudaGetSymbolAddress(&ph, d_h);
    float* xp = (float*)px;
    float* hp = (float*)ph;

    init_kernel<<<(N_NODES * HEADS + 255) / 256, 256>>>();

    // x = emb_table[code] @ W_feat + b_feat
    gemm_kernel<<<dim3(EMB / 64, N_NODES / 64), 256>>>(emb, code, W_feat, b_feat, xp, EMB, EMB);
    // h = x @ W_gat
    gemm_kernel<<<dim3(OUT / 64, N_NODES / 64), 256>>>(xp, nullptr, W_gat, nullptr, hp, EMB, OUT);

    attn_kernel<<<N_NODES, 128>>>(att_src, att_dst);

    count_kernel<<<(NTOT + 255) / 256, 256>>>(ei);
    scan_kernel<<<1, 1024>>>();
    scatter_kernel<<<(NTOT + 255) / 256, 256>>>(ei);

    alpha1_kernel<<<(NTOT + 255) / 256, 256>>>(ei);
    alpha2_kernel<<<(NTOT + 255) / 256, 256>>>(ei);

    aggregate_kernel<<<N_NODES, 256>>>(ei, bias_gat);

    gbound_kernel<<<(N_NODES + 255) / 256, 256>>>(batch);
    gfix_kernel<<<1, 32>>>();
    pool_kernel<<<dim3(OUT / 128, NB), 128>>>();

    mlp_kernel<<<dim3(NB, 2), 128>>>(W1r, b1r, W2r, b2r, W1m, b1m, W2m, b2m, out);
}

// round 3
// speedup vs baseline: 1.8060x; 1.8060x over previous
#include <cuda_runtime.h>
#include <cuda_bf16.h>
#include <math.h>

#define N_NODES 32768
#define EMB 512
#define HEADS 4
#define OUT 2048      // EMB*HEADS
#define NE 131072     // directed edges
#define NTOT (NE + N_NODES)  // with self loops
#define NB 32         // graphs
#define HID 32

#define BM 128
#define BN 64
#define BK 32
#define KPAD 40       // halves per smem row (stride) -> conflict-free frags

// ---------------- scratch (static device globals; no allocs allowed) -------
__device__ __nv_bfloat16 d_xhi[(size_t)N_NODES * EMB];
__device__ __nv_bfloat16 d_xlo[(size_t)N_NODES * EMB];
__device__ float    d_h[(size_t)N_NODES * OUT];        // after W_gat
__device__ float    d_of[(size_t)N_NODES * OUT];       // GAT output (post act)
__device__ __nv_bfloat16 d_wfhi[(size_t)EMB * EMB];    // W_feat^T bf16 hi [N][K]
__device__ __nv_bfloat16 d_wflo[(size_t)EMB * EMB];
__device__ __nv_bfloat16 d_wghi[(size_t)OUT * EMB];    // W_gat^T bf16 hi [N][K]
__device__ __nv_bfloat16 d_wglo[(size_t)OUT * EMB];
__device__ float    d_asrc[N_NODES * HEADS];
__device__ float    d_adst[N_NODES * HEADS];
__device__ float    d_alpha[(size_t)NTOT * HEADS];
__device__ unsigned d_amax[N_NODES * HEADS];
__device__ float    d_denom[N_NODES * HEADS];
__device__ int      d_deg[N_NODES];
__device__ int      d_off[N_NODES + 1];
__device__ int      d_pos[N_NODES];
__device__ int      d_eidx[NTOT];
__device__ float    d_g[NB * 2 * OUT];
__device__ int      d_gstart[NB + 1];

// monotonic float<->uint encoding for atomicMax on signed floats
__device__ __forceinline__ unsigned fenc(float f) {
    unsigned u = __float_as_uint(f);
    return (u >> 31) ? ~u : (u | 0x80000000u);
}
__device__ __forceinline__ float fdec(unsigned u) {
    u = (u >> 31) ? (u & 0x7fffffffu) : ~u;
    return __uint_as_float(u);
}

__device__ __forceinline__ void dec2(float v, __nv_bfloat16& h, __nv_bfloat16& l) {
    h = __float2bfloat16_rn(v);
    l = __float2bfloat16_rn(v - __bfloat162float(h));
}

__device__ __forceinline__ void mma16816(float* c, const unsigned* a, const unsigned* b) {
    asm volatile(
        "mma.sync.aligned.m16n8k16.row.col.f32.bf16.bf16.f32 "
        "{%0,%1,%2,%3}, {%4,%5,%6,%7}, {%8,%9}, {%0,%1,%2,%3};"
        : "+f"(c[0]), "+f"(c[1]), "+f"(c[2]), "+f"(c[3])
        : "r"(a[0]), "r"(a[1]), "r"(a[2]), "r"(a[3]), "r"(b[0]), "r"(b[1]));
}

// ---------------- init ------------------------------------------------------
__global__ void init_kernel() {
    int i = blockIdx.x * blockDim.x + threadIdx.x;
    if (i < N_NODES * HEADS) { d_amax[i] = 0u; d_denom[i] = 0.f; }
    if (i < N_NODES) d_deg[i] = 0;
    if (i <= NB) d_gstart[i] = N_NODES;
}

// ---------------- weight prep: transpose fp32 [K][N] -> bf16 hi/lo [N][K] ---
__global__ void prepW_kernel(const float* __restrict__ W, int K, int N,
                             __nv_bfloat16* __restrict__ Whi,
                             __nv_bfloat16* __restrict__ Wlo) {
    __shared__ float tile[32][33];
    int kx = blockIdx.y * 32, nx = blockIdx.x * 32;
    int tx = threadIdx.x & 31, ty = threadIdx.x >> 5;  // 256 threads: 8 rows/pass
#pragma unroll
    for (int p = 0; p < 4; p++)
        tile[ty + p * 8][tx] = W[(long)(kx + ty + p * 8) * N + nx + tx];
    __syncthreads();
#pragma unroll
    for (int p = 0; p < 4; p++) {
        int nl = ty + p * 8, kl = tx;
        float v = tile[kl][nl];
        __nv_bfloat16 h, l;
        dec2(v, h, l);
        long o = (long)(nx + nl) * K + kx + kl;
        Whi[o] = h;
        Wlo[o] = l;
    }
}

// ---------------- bf16x3 tensor-core GEMM ----------------------------------
// C[M,Ncols] = A[M,K] @ W[K,Ncols]; B provided pre-transposed bf16 hi/lo [Ncols][K].
// GATHER_FP32A: A is fp32 with row-gather (decomposed at smem store).
// EPI_BF16: write bf16 hi/lo output (+bias); else fp32 output (+optional bias).
template <bool GATHER_FP32A, bool EPI_BF16>
__global__ void gemm_bf16x3_kernel(
    const float* __restrict__ Af, const int* __restrict__ gather,
    const __nv_bfloat16* __restrict__ Ahi, const __nv_bfloat16* __restrict__ Alo,
    const __nv_bfloat16* __restrict__ Bhi, const __nv_bfloat16* __restrict__ Blo,
    const float* __restrict__ bias,
    float* __restrict__ Cf,
    __nv_bfloat16* __restrict__ Chi, __nv_bfloat16* __restrict__ Clo,
    int K, int Ncols) {
    __shared__ __nv_bfloat16 As_hi[BM][KPAD];
    __shared__ __nv_bfloat16 As_lo[BM][KPAD];
    __shared__ __nv_bfloat16 Bs_hi[BN][KPAD];
    __shared__ __nv_bfloat16 Bs_lo[BN][KPAD];

    int tid = threadIdx.x;             // 256
    int wid = tid >> 5, lane = tid & 31;
    int warp_m = wid >> 1, warp_n = wid & 1;
    int g = lane >> 2, t = lane & 3;
    int brow = blockIdx.y * BM, bcol = blockIdx.x * BN;

    // A source pointers
    const float* aptr_f[4];
    const __nv_bfloat16 *aptr_h[2], *aptr_l[2];
    if (GATHER_FP32A) {
        int ar = tid >> 3, ac = (tid & 7) * 4;
#pragma unroll
        for (int i = 0; i < 4; i++) {
            int grow = brow + ar + i * 32;
            long r = gather ? (long)gather[grow] : (long)grow;
            aptr_f[i] = Af + r * (long)K + ac;
        }
    } else {
        int ar = tid >> 2, ac = (tid & 3) * 8;
#pragma unroll
        for (int i = 0; i < 2; i++) {
            long r = brow + ar + i * 64;
            aptr_h[i] = Ahi + r * (long)K + ac;
            aptr_l[i] = Alo + r * (long)K + ac;
        }
    }
    const __nv_bfloat16* bptr_h = Bhi + (long)(bcol + (tid >> 2)) * K + (tid & 3) * 8;
    const __nv_bfloat16* bptr_l = Blo + (long)(bcol + (tid >> 2)) * K + (tid & 3) * 8;

    float acc[2][4][4];
#pragma unroll
    for (int mi = 0; mi < 2; mi++)
#pragma unroll
        for (int ni = 0; ni < 4; ni++)
#pragma unroll
            for (int j = 0; j < 4; j++) acc[mi][ni][j] = 0.f;

    for (int kk = 0; kk < K; kk += BK) {
        // ---- load tiles ----
        if (GATHER_FP32A) {
            int ar = tid >> 3, ac = (tid & 7) * 4;
#pragma unroll
            for (int i = 0; i < 4; i++) {
                float4 v = *(const float4*)(aptr_f[i] + kk);
                int row = ar + i * 32;
                __nv_bfloat16 h0, l0, h1, l1, h2, l2, h3, l3;
                dec2(v.x, h0, l0); dec2(v.y, h1, l1);
                dec2(v.z, h2, l2); dec2(v.w, h3, l3);
                As_hi[row][ac + 0] = h0; As_hi[row][ac + 1] = h1;
                As_hi[row][ac + 2] = h2; As_hi[row][ac + 3] = h3;
                As_lo[row][ac + 0] = l0; As_lo[row][ac + 1] = l1;
                As_lo[row][ac + 2] = l2; As_lo[row][ac + 3] = l3;
            }
        } else {
            int ar = tid >> 2, ac = (tid & 3) * 8;
#pragma unroll
            for (int i = 0; i < 2; i++) {
                uint4 vh = *(const uint4*)(aptr_h[i] + kk);
                uint4 vl = *(const uint4*)(aptr_l[i] + kk);
                *(uint4*)&As_hi[ar + i * 64][ac] = vh;
                *(uint4*)&As_lo[ar + i * 64][ac] = vl;
            }
        }
        {
            int n = tid >> 2, ac = (tid & 3) * 8;
            uint4 vh = *(const uint4*)(bptr_h + kk);
            uint4 vl = *(const uint4*)(bptr_l + kk);
            *(uint4*)&Bs_hi[n][ac] = vh;
            *(uint4*)&Bs_lo[n][ac] = vl;
        }
        __syncthreads();

        // ---- compute: 2 k-steps of 16 ----
#pragma unroll
        for (int ks = 0; ks < 2; ks++) {
            int k0 = ks * 16;
            unsigned ah[2][4], al[2][4];
#pragma unroll
            for (int mi = 0; mi < 2; mi++) {
                int r = warp_m * 32 + mi * 16 + g;
                ah[mi][0] = *(const unsigned*)&As_hi[r][k0 + 2 * t];
                ah[mi][1] = *(const unsigned*)&As_hi[r + 8][k0 + 2 * t];
                ah[mi][2] = *(const unsigned*)&As_hi[r][k0 + 2 * t + 8];
                ah[mi][3] = *(const unsigned*)&As_hi[r + 8][k0 + 2 * t + 8];
                al[mi][0] = *(const unsigned*)&As_lo[r][k0 + 2 * t];
                al[mi][1] = *(const unsigned*)&As_lo[r + 8][k0 + 2 * t];
                al[mi][2] = *(const unsigned*)&As_lo[r][k0 + 2 * t + 8];
                al[mi][3] = *(const unsigned*)&As_lo[r + 8][k0 + 2 * t + 8];
            }
            unsigned bh[4][2], bl[4][2];
#pragma unroll
            for (int ni = 0; ni < 4; ni++) {
                int c = warp_n * 32 + ni * 8 + g;
                bh[ni][0] = *(const unsigned*)&Bs_hi[c][k0 + 2 * t];
                bh[ni][1] = *(const unsigned*)&Bs_hi[c][k0 + 2 * t + 8];
                bl[ni][0] = *(const unsigned*)&Bs_lo[c][k0 + 2 * t];
                bl[ni][1] = *(const unsigned*)&Bs_lo[c][k0 + 2 * t + 8];
            }
#pragma unroll
            for (int mi = 0; mi < 2; mi++)
#pragma unroll
                for (int ni = 0; ni < 4; ni++) {
                    mma16816(acc[mi][ni], ah[mi], bl[ni]);
                    mma16816(acc[mi][ni], al[mi], bh[ni]);
                    mma16816(acc[mi][ni], ah[mi], bh[ni]);
                }
        }
        __syncthreads();
    }

    // ---- epilogue ----
#pragma unroll
    for (int mi = 0; mi < 2; mi++) {
        int r0 = brow + warp_m * 32 + mi * 16 + g;
#pragma unroll
        for (int ni = 0; ni < 4; ni++) {
            int c0 = bcol + warp_n * 32 + ni * 8 + 2 * t;
            float b0 = bias ? bias[c0] : 0.f;
            float b1 = bias ? bias[c0 + 1] : 0.f;
            float v0 = acc[mi][ni][0] + b0;
            float v1 = acc[mi][ni][1] + b1;
            float v2 = acc[mi][ni][2] + b0;
            float v3 = acc[mi][ni][3] + b1;
            if (EPI_BF16) {
                __nv_bfloat16 h0, l0, h1, l1;
                dec2(v0, h0, l0); dec2(v1, h1, l1);
                __nv_bfloat162 hp; hp.x = h0; hp.y = h1;
                __nv_bfloat162 lp; lp.x = l0; lp.y = l1;
                *(__nv_bfloat162*)&Chi[(long)r0 * Ncols + c0] = hp;
                *(__nv_bfloat162*)&Clo[(long)r0 * Ncols + c0] = lp;
                dec2(v2, h0, l0); dec2(v3, h1, l1);
                hp.x = h0; hp.y = h1; lp.x = l0; lp.y = l1;
                *(__nv_bfloat162*)&Chi[(long)(r0 + 8) * Ncols + c0] = hp;
                *(__nv_bfloat162*)&Clo[(long)(r0 + 8) * Ncols + c0] = lp;
            } else {
                float2 p0 = make_float2(v0, v1);
                float2 p1 = make_float2(v2, v3);
                *(float2*)&Cf[(long)r0 * Ncols + c0] = p0;
                *(float2*)&Cf[(long)(r0 + 8) * Ncols + c0] = p1;
            }
        }
    }
}

// ---------------- per-node attention scalars (float4) -----------------------
__global__ void attn_kernel(const float* __restrict__ att_src,
                            const float* __restrict__ att_dst) {
    int n = blockIdx.x;
    int w = threadIdx.x >> 5, lane = threadIdx.x & 31;
    const float4* hr = (const float4*)(d_h + (size_t)n * OUT + w * EMB);
    const float4* as = (const float4*)(att_src + w * EMB);
    const float4* ad = (const float4*)(att_dst + w * EMB);
    float s1 = 0.f, s2 = 0.f;
#pragma unroll
    for (int c = lane; c < EMB / 4; c += 32) {
        float4 v = hr[c], a = as[c], d = ad[c];
        s1 += v.x * a.x + v.y * a.y + v.z * a.z + v.w * a.w;
        s2 += v.x * d.x + v.y * d.y + v.z * d.z + v.w * d.w;
    }
#pragma unroll
    for (int o = 16; o; o >>= 1) {
        s1 += __shfl_down_sync(0xffffffffu, s1, o);
        s2 += __shfl_down_sync(0xffffffffu, s2, o);
    }
    if (lane == 0) { d_asrc[n * 4 + w] = s1; d_adst[n * 4 + w] = s2; }
}

// ---------------- CSR build -------------------------------------------------
__global__ void count_kernel(const int* __restrict__ ei) {
    int e = blockIdx.x * blockDim.x + threadIdx.x;
    if (e >= NTOT) return;
    int dst = (e < NE) ? ei[NE + e] : (e - NE);
    atomicAdd(&d_deg[dst], 1);
}

__global__ void scan_kernel() {  // 1 block, 1024 threads
    __shared__ int sh[1024];
    __shared__ int carry;
    int tid = threadIdx.x;
    if (tid == 0) carry = 0;
    __syncthreads();
    for (int ch = 0; ch < N_NODES / 1024; ch++) {
        int i = ch * 1024 + tid;
        int v = d_deg[i];
        sh[tid] = v;
        __syncthreads();
        for (int o = 1; o < 1024; o <<= 1) {
            int x = (tid >= o) ? sh[tid - o] : 0;
            __syncthreads();
            sh[tid] += x;
            __syncthreads();
        }
        int excl = carry + sh[tid] - v;
        d_off[i] = excl;
        d_pos[i] = excl;
        __syncthreads();
        if (tid == 1023) carry += sh[1023];
        __syncthreads();
    }
    if (tid == 0) d_off[N_NODES] = carry;
}

__global__ void scatter_kernel(const int* __restrict__ ei) {
    int e = blockIdx.x * blockDim.x + threadIdx.x;
    if (e >= NTOT) return;
    int dst = (e < NE) ? ei[NE + e] : (e - NE);
    int p = atomicAdd(&d_pos[dst], 1);
    d_eidx[p] = e;
}

// ---------------- softmax passes -------------------------------------------
__global__ void alpha1_kernel(const int* __restrict__ ei) {
    int e = blockIdx.x * blockDim.x + threadIdx.x;
    if (e >= NTOT) return;
    int src, dst;
    if (e < NE) { src = ei[e]; dst = ei[NE + e]; }
    else        { src = dst = e - NE; }
    float4 as = *(const float4*)&d_asrc[src * 4];
    float4 ad = *(const float4*)&d_adst[dst * 4];
    float r[4] = {as.x + ad.x, as.y + ad.y, as.z + ad.z, as.w + ad.w};
#pragma unroll
    for (int h = 0; h < 4; h++) {
        r[h] = r[h] > 0.f ? r[h] : 0.2f * r[h];
        atomicMax(&d_amax[dst * 4 + h], fenc(r[h]));
    }
    *(float4*)&d_alpha[(size_t)e * 4] = make_float4(r[0], r[1], r[2], r[3]);
}

__global__ void alpha2_kernel(const int* __restrict__ ei) {
    int e = blockIdx.x * blockDim.x + threadIdx.x;
    if (e >= NTOT) return;
    int dst = (e < NE) ? ei[NE + e] : (e - NE);
    float4 r = *(const float4*)&d_alpha[(size_t)e * 4];
    float a0 = expf(r.x - fdec(d_amax[dst * 4 + 0]));
    float a1 = expf(r.y - fdec(d_amax[dst * 4 + 1]));
    float a2 = expf(r.z - fdec(d_amax[dst * 4 + 2]));
    float a3 = expf(r.w - fdec(d_amax[dst * 4 + 3]));
    *(float4*)&d_alpha[(size_t)e * 4] = make_float4(a0, a1, a2, a3);
    atomicAdd(&d_denom[dst * 4 + 0], a0);
    atomicAdd(&d_denom[dst * 4 + 1], a1);
    atomicAdd(&d_denom[dst * 4 + 2], a2);
    atomicAdd(&d_denom[dst * 4 + 3], a3);
}

// ---------------- message aggregation (CSR, no atomics) ---------------------
__global__ void aggregate_kernel(const int* __restrict__ ei,
                                 const float* __restrict__ bias_gat) {
    int dst = blockIdx.x, t = threadIdx.x;  // 256 threads
    float acc[8] = {0.f, 0.f, 0.f, 0.f, 0.f, 0.f, 0.f, 0.f};
    int s = d_off[dst], e = d_off[dst + 1];
    float4 dn = *(const float4*)&d_denom[dst * 4];
    float inv0 = 1.f / (dn.x + 1e-16f);
    float inv1 = 1.f / (dn.y + 1e-16f);
    float inv2 = 1.f / (dn.z + 1e-16f);
    float inv3 = 1.f / (dn.w + 1e-16f);
    for (int i = s; i < e; i++) {
        int ed = d_eidx[i];
        int src = (ed < NE) ? ei[ed] : (ed - NE);
        float4 al = *(const float4*)&d_alpha[(size_t)ed * 4];
        float c0 = al.x * inv0, c1 = al.y * inv1, c2 = al.z * inv2, c3 = al.w * inv3;
        const float* hr = d_h + (size_t)src * OUT;
        acc[0] += hr[t +    0] * c0;
        acc[1] += hr[t +  256] * c0;
        acc[2] += hr[t +  512] * c1;
        acc[3] += hr[t +  768] * c1;
        acc[4] += hr[t + 1024] * c2;
        acc[5] += hr[t + 1280] * c2;
        acc[6] += hr[t + 1536] * c3;
        acc[7] += hr[t + 1792] * c3;
    }
#pragma unroll
    for (int j = 0; j < 8; j++) {
        int c = t + 256 * j;
        float v = acc[j] + bias_gat[c];
        v = v > 0.f ? v : 0.01f * v;   // outer leaky_relu (default slope 0.01)
        d_of[(size_t)dst * OUT + c] = v;
    }
}

// ---------------- graph boundaries + pooling --------------------------------
__global__ void gbound_kernel(const int* __restrict__ batch) {
    int i = blockIdx.x * blockDim.x + threadIdx.x;
    if (i >= N_NODES) return;
    atomicMin(&d_gstart[batch[i]], i);
}

__global__ void gfix_kernel() {
    if (threadIdx.x == 0) {
        d_gstart[NB] = N_NODES;
        for (int b = NB - 1; b >= 0; b--)
            if (d_gstart[b] > d_gstart[b + 1]) d_gstart[b] = d_gstart[b + 1];
    }
}

__global__ void pool_kernel() {  // grid (16, NB), 128 threads
    int b = blockIdx.y;
    int c = blockIdx.x * 128 + threadIdx.x;
    int s = d_gstart[b], e = d_gstart[b + 1];
    float sum = 0.f, mx = -INFINITY;
    for (int i = s; i < e; i++) {
        float v = d_of[(size_t)i * OUT + c];
        sum += v;
        mx = fmaxf(mx, v);
    }
    float cnt = (float)(e - s);
    d_g[b * 2 * OUT + c] = sum / fmaxf(cnt, 1.f);
    d_g[b * 2 * OUT + OUT + c] = mx;
}

// ---------------- head MLPs -------------------------------------------------
__global__ void mlp_kernel(const float* __restrict__ W1r, const float* __restrict__ b1r,
                           const float* __restrict__ W2r, const float* __restrict__ b2r,
                           const float* __restrict__ W1m, const float* __restrict__ b1m,
                           const float* __restrict__ W2m, const float* __restrict__ b2m,
                           float* __restrict__ out) {
    int b = blockIdx.x, task = blockIdx.y;
    const float* W1 = task ? W1m : W1r;
    const float* b1 = task ? b1m : b1r;
    const float* W2 = task ? W2m : W2r;
    const float* b2 = task ? b2m : b2r;
    __shared__ float gs[2 * OUT];
    __shared__ float part[128];
    int t = threadIdx.x;  // 128
    for (int k = t; k < 2 * OUT; k += 128) gs[k] = d_g[b * 2 * OUT + k];
    __syncthreads();
    int j = t & 31, seg = t >> 5;
    float s = 0.f;
    for (int k = seg; k < 2 * OUT; k += 4) s += gs[k] * W1[k * HID + j];
    part[t] = s;
    __syncthreads();
    if (t < 32) {
        float hj = part[t] + part[t + 32] + part[t + 64] + part[t + 96] + b1[t];
        hj = fmaxf(hj, 0.f);
        float p = hj * W2[t];
#pragma unroll
        for (int o = 16; o; o >>= 1) p += __shfl_down_sync(0xffffffffu, p, o);
        if (t == 0) out[task * NB + b] = p + b2[0];
    }
}

// ---------------- launch ----------------------------------------------------
extern "C" void kernel_launch(void* const* d_in, const int* in_sizes, int n_in,
                              void* d_out, int out_size) {
    const int*   code     = (const int*)d_in[0];
    const int*   ei       = (const int*)d_in[1];
    const int*   batch    = (const int*)d_in[2];
    const float* emb      = (const float*)d_in[3];
    const float* W_feat   = (const float*)d_in[4];
    const float* b_feat   = (const float*)d_in[5];
    const float* W_gat    = (const float*)d_in[6];
    const float* att_src  = (const float*)d_in[7];
    const float* att_dst  = (const float*)d_in[8];
    const float* bias_gat = (const float*)d_in[9];
    const float* W1r = (const float*)d_in[10];
    const float* b1r = (const float*)d_in[11];
    const float* W2r = (const float*)d_in[12];
    const float* b2r = (const float*)d_in[13];
    const float* W1m = (const float*)d_in[14];
    const float* b1m = (const float*)d_in[15];
    const float* W2m = (const float*)d_in[16];
    const float* b2m = (const float*)d_in[17];
    float* out = (float*)d_out;

    void *p0, *p1, *p2, *p3, *p4, *p5, *p6, *p7, *p8;
    cudaGetSymbolAddress(&p0, d_xhi);
    cudaGetSymbolAddress(&p1, d_xlo);
    cudaGetSymbolAddress(&p2, d_h);
    cudaGetSymbolAddress(&p3, d_wfhi);
    cudaGetSymbolAddress(&p4, d_wflo);
    cudaGetSymbolAddress(&p5, d_wghi);
    cudaGetSymbolAddress(&p6, d_wglo);
    __nv_bfloat16* xhi  = (__nv_bfloat16*)p0;
    __nv_bfloat16* xlo  = (__nv_bfloat16*)p1;
    float*         hp   = (float*)p2;
    __nv_bfloat16* wfhi = (__nv_bfloat16*)p3;
    __nv_bfloat16* wflo = (__nv_bfloat16*)p4;
    __nv_bfloat16* wghi = (__nv_bfloat16*)p5;
    __nv_bfloat16* wglo = (__nv_bfloat16*)p6;

    init_kernel<<<(N_NODES * HEADS + 255) / 256, 256>>>();

    // prep weights: transpose + bf16 hi/lo split
    prepW_kernel<<<dim3(EMB / 32, EMB / 32), 256>>>(W_feat, EMB, EMB, wfhi, wflo);
    prepW_kernel<<<dim3(OUT / 32, EMB / 32), 256>>>(W_gat, EMB, OUT, wghi, wglo);

    // x = emb_table[code] @ W_feat + b_feat  -> bf16 hi/lo
    gemm_bf16x3_kernel<true, true><<<dim3(EMB / BN, N_NODES / BM), 256>>>(
        emb, code, nullptr, nullptr, wfhi, wflo, b_feat,
        nullptr, xhi, xlo, EMB, EMB);

    // h = x @ W_gat -> fp32
    gemm_bf16x3_kernel<false, false><<<dim3(OUT / BN, N_NODES / BM), 256>>>(
        nullptr, nullptr, xhi, xlo, wghi, wglo, nullptr,
        hp, nullptr, nullptr, EMB, OUT);

    attn_kernel<<<N_NODES, 128>>>(att_src, att_dst);

    count_kernel<<<(NTOT + 255) / 256, 256>>>(ei);
    scan_kernel<<<1, 1024>>>();
    scatter_kernel<<<(NTOT + 255) / 256, 256>>>(ei);

    alpha1_kernel<<<(NTOT + 255) / 256, 256>>>(ei);
    alpha2_kernel<<<(NTOT + 255) / 256, 256>>>(ei);

    aggregate_kernel<<<N_NODES, 256>>>(ei, bias_gat);

    gbound_kernel<<<(N_NODES + 255) / 256, 256>>>(batch);
    gfix_kernel<<<1, 32>>>();
    pool_kernel<<<dim3(OUT / 128, NB), 128>>>();

    mlp_kernel<<<dim3(NB, 2), 128>>>(W1r, b1r, W2r, b2r, W1m, b1m, W2m, b2m, out);
}

// round 5
// speedup vs baseline: 2.2055x; 1.2212x over previous
#include <cuda_runtime.h>
#include <cuda_bf16.h>
#include <math.h>

#define N_NODES 32768
#define EMB 512
#define HEADS 4
#define OUT 2048
#define NE 131072
#define NTOT (NE + N_NODES)
#define NB 32
#define HID 32

#define BM 128
#define BN 64
#define BKC 64            // k-chunk (bf16 elems) = 128 bytes/row
#define GEMM_STAGE_BYTES 49152   // (128+128+64+64)*128 bytes
#define GEMM_SMEM (2 * GEMM_STAGE_BYTES)

// ---------------- scratch (static device globals) ---------------------------
__device__ __nv_bfloat16 d_xehi[(size_t)N_NODES * EMB];  // gathered emb hi
__device__ __nv_bfloat16 d_xelo[(size_t)N_NODES * EMB];
__device__ __nv_bfloat16 d_xhi[(size_t)N_NODES * EMB];   // after feat linear
__device__ __nv_bfloat16 d_xlo[(size_t)N_NODES * EMB];
__device__ __nv_bfloat16 d_hhi[(size_t)N_NODES * OUT];   // after W_gat
__device__ __nv_bfloat16 d_hlo[(size_t)N_NODES * OUT];
__device__ float    d_of[(size_t)N_NODES * OUT];         // GAT out (post act)
__device__ __nv_bfloat16 d_wfhi[(size_t)EMB * EMB];
__device__ __nv_bfloat16 d_wflo[(size_t)EMB * EMB];
__device__ __nv_bfloat16 d_wghi[(size_t)OUT * EMB];
__device__ __nv_bfloat16 d_wglo[(size_t)OUT * EMB];
__device__ float    d_asrc[N_NODES * HEADS];
__device__ float    d_adst[N_NODES * HEADS];
__device__ float    d_alpha[(size_t)NTOT * HEADS];
__device__ unsigned d_amax[N_NODES * HEADS];
__device__ float    d_denom[N_NODES * HEADS];
__device__ int      d_deg[N_NODES];
__device__ int      d_off[N_NODES + 1];
__device__ int      d_pos[N_NODES];
__device__ int      d_eidx[NTOT];
__device__ float    d_g[NB * 2 * OUT];
__device__ int      d_gstart[NB + 1];

__device__ __forceinline__ unsigned fenc(float f) {
    unsigned u = __float_as_uint(f);
    return (u >> 31) ? ~u : (u | 0x80000000u);
}
__device__ __forceinline__ float fdec(unsigned u) {
    u = (u >> 31) ? (u & 0x7fffffffu) : ~u;
    return __uint_as_float(u);
}
__device__ __forceinline__ void dec2(float v, __nv_bfloat16& h, __nv_bfloat16& l) {
    h = __float2bfloat16_rn(v);
    l = __float2bfloat16_rn(v - __bfloat162float(h));
}
__device__ __forceinline__ void mma16816(float* c, const unsigned* a, const unsigned* b) {
    asm volatile(
        "mma.sync.aligned.m16n8k16.row.col.f32.bf16.bf16.f32 "
        "{%0,%1,%2,%3}, {%4,%5,%6,%7}, {%8,%9}, {%0,%1,%2,%3};"
        : "+f"(c[0]), "+f"(c[1]), "+f"(c[2]), "+f"(c[3])
        : "r"(a[0]), "r"(a[1]), "r"(a[2]), "r"(a[3]), "r"(b[0]), "r"(b[1]));
}
__device__ __forceinline__ void ldsm_x4(unsigned* r, unsigned addr) {
    asm volatile("ldmatrix.sync.aligned.m8n8.x4.shared.b16 {%0,%1,%2,%3}, [%4];"
                 : "=r"(r[0]), "=r"(r[1]), "=r"(r[2]), "=r"(r[3]) : "r"(addr));
}
__device__ __forceinline__ void cpasync16(unsigned saddr, const void* gaddr) {
    asm volatile("cp.async.cg.shared.global [%0], [%1], 16;" :: "r"(saddr), "l"(gaddr));
}
__device__ __forceinline__ void cpcommit() { asm volatile("cp.async.commit_group;"); }
__device__ __forceinline__ void cpwaitall() { asm volatile("cp.async.wait_group 0;"); }

// ---------------- init ------------------------------------------------------
__global__ void init_kernel() {
    int i = blockIdx.x * blockDim.x + threadIdx.x;
    if (i < N_NODES * HEADS) { d_amax[i] = 0u; d_denom[i] = 0.f; }
    if (i < N_NODES) d_deg[i] = 0;
    if (i <= NB) d_gstart[i] = N_NODES;
}

// ---------------- weight prep: transpose fp32 [K][N] -> bf16 hi/lo [N][K] ---
__global__ void prepW_kernel(const float* __restrict__ W, int K, int N,
                             __nv_bfloat16* __restrict__ Whi,
                             __nv_bfloat16* __restrict__ Wlo) {
    __shared__ float tile[32][33];
    int kx = blockIdx.y * 32, nx = blockIdx.x * 32;
    int tx = threadIdx.x & 31, ty = threadIdx.x >> 5;
#pragma unroll
    for (int p = 0; p < 4; p++)
        tile[ty + p * 8][tx] = W[(long)(kx + ty + p * 8) * N + nx + tx];
    __syncthreads();
#pragma unroll
    for (int p = 0; p < 4; p++) {
        int nl = ty + p * 8, kl = tx;
        float v = tile[kl][nl];
        __nv_bfloat16 h, l;
        dec2(v, h, l);
        long o = (long)(nx + nl) * K + kx + kl;
        Whi[o] = h;
        Wlo[o] = l;
    }
}

// ---------------- gather emb rows + decompose to bf16 hi/lo -----------------
__global__ void gathdec_kernel(const float* __restrict__ emb,
                               const int* __restrict__ code) {
    long i = (long)blockIdx.x * blockDim.x + threadIdx.x;  // N*EMB/4 threads
    int row = (int)(i >> 7);
    int c4 = (int)(i & 127) * 4;
    float4 v = *(const float4*)(emb + (long)code[row] * EMB + c4);
    __nv_bfloat16 h0, l0, h1, l1, h2, l2, h3, l3;
    dec2(v.x, h0, l0); dec2(v.y, h1, l1);
    dec2(v.z, h2, l2); dec2(v.w, h3, l3);
    long o = (long)row * EMB + c4;
    __nv_bfloat162 p;
    p.x = h0; p.y = h1; *(__nv_bfloat162*)&d_xehi[o] = p;
    p.x = h2; p.y = h3; *(__nv_bfloat162*)&d_xehi[o + 2] = p;
    p.x = l0; p.y = l1; *(__nv_bfloat162*)&d_xelo[o] = p;
    p.x = l2; p.y = l3; *(__nv_bfloat162*)&d_xelo[o + 2] = p;
}

// ---------------- bf16x3 tensor-core GEMM (cp.async + ldmatrix) -------------
// C = A @ B^T with A[M][K], B[Ncols][K] bf16 hi/lo. Output bf16 hi/lo (+bias).
__global__ void __launch_bounds__(256, 2) gemm_fast_kernel(
    const __nv_bfloat16* __restrict__ Ahi, const __nv_bfloat16* __restrict__ Alo,
    const __nv_bfloat16* __restrict__ Bhi, const __nv_bfloat16* __restrict__ Blo,
    const float* __restrict__ bias,
    __nv_bfloat16* __restrict__ Chi, __nv_bfloat16* __restrict__ Clo,
    int K, int Ncols) {
    extern __shared__ char smem[];
    unsigned sbase = (unsigned)__cvta_generic_to_shared(smem);

    int tid = threadIdx.x;
    int wid = tid >> 5, lane = tid & 31;
    int warp_m = wid >> 1, warp_n = wid & 1;
    int brow = blockIdx.y * BM, bcol = blockIdx.x * BN;

    // cp.async assignments (per stage: A 4+4 chunks/thread, B 2+2)
    int arow[4], ach[4], brow_l[2], bch[2];
    const __nv_bfloat16 *agp_h[4], *agp_l[4], *bgp_h[2], *bgp_l[2];
    unsigned asm_h[4], asm_l[4], bsm_h[2], bsm_l[2];
#pragma unroll
    for (int p = 0; p < 4; p++) {
        int id = tid + 256 * p;
        arow[p] = id >> 3; ach[p] = id & 7;
        agp_h[p] = Ahi + (long)(brow + arow[p]) * K + ach[p] * 8;
        agp_l[p] = Alo + (long)(brow + arow[p]) * K + ach[p] * 8;
        unsigned so = arow[p] * 128 + ((ach[p] ^ (arow[p] & 7)) << 4);
        asm_h[p] = so;
        asm_l[p] = 16384 + so;
    }
#pragma unroll
    for (int p = 0; p < 2; p++) {
        int id = tid + 256 * p;
        brow_l[p] = id >> 3; bch[p] = id & 7;
        bgp_h[p] = Bhi + (long)(bcol + brow_l[p]) * K + bch[p] * 8;
        bgp_l[p] = Blo + (long)(bcol + brow_l[p]) * K + bch[p] * 8;
        unsigned so = brow_l[p] * 128 + ((bch[p] ^ (brow_l[p] & 7)) << 4);
        bsm_h[p] = 32768 + so;
        bsm_l[p] = 40960 + so;
    }

    float acc[2][4][4];
#pragma unroll
    for (int mi = 0; mi < 2; mi++)
#pragma unroll
        for (int ni = 0; ni < 4; ni++)
#pragma unroll
            for (int j = 0; j < 4; j++) acc[mi][ni][j] = 0.f;

    int nch = K / BKC;
    // prologue: load chunk 0 into stage 0
    {
        unsigned sb = sbase;
#pragma unroll
        for (int p = 0; p < 4; p++) {
            cpasync16(sb + asm_h[p], agp_h[p]);
            cpasync16(sb + asm_l[p], agp_l[p]);
        }
#pragma unroll
        for (int p = 0; p < 2; p++) {
            cpasync16(sb + bsm_h[p], bgp_h[p]);
            cpasync16(sb + bsm_l[p], bgp_l[p]);
        }
        cpcommit();
    }

    // per-warp ldmatrix lane addressing (static parts)
    int a_lrow = (lane & 15);
    int a_lchsel = (lane >> 4);           // 0/1
    int b_lrow = (lane & 7) + ((lane >> 4) << 3);
    int b_lchsel = (lane >> 3) & 1;

    for (int ch = 0; ch < nch; ch++) {
        cpwaitall();
        __syncthreads();
        unsigned cur = sbase + (unsigned)(ch & 1) * GEMM_STAGE_BYTES;
        if (ch + 1 < nch) {
            unsigned nxt = sbase + (unsigned)((ch + 1) & 1) * GEMM_STAGE_BYTES;
            int kk = (ch + 1) * BKC;
#pragma unroll
            for (int p = 0; p < 4; p++) {
                cpasync16(nxt + asm_h[p], agp_h[p] + kk);
                cpasync16(nxt + asm_l[p], agp_l[p] + kk);
            }
#pragma unroll
            for (int p = 0; p < 2; p++) {
                cpasync16(nxt + bsm_h[p], bgp_h[p] + kk);
                cpasync16(nxt + bsm_l[p], bgp_l[p] + kk);
            }
            cpcommit();
        }

#pragma unroll
        for (int ks = 0; ks < 4; ks++) {
            int cb = ks << 1;
            unsigned ah[2][4], al_[2][4];
#pragma unroll
            for (int mi = 0; mi < 2; mi++) {
                int row = warp_m * 32 + mi * 16 + a_lrow;
                int c = cb + a_lchsel;
                unsigned off = row * 128 + (((unsigned)(c ^ (row & 7))) << 4);
                ldsm_x4(ah[mi], cur + off);
                ldsm_x4(al_[mi], cur + 16384 + off);
            }
            unsigned bh[4][2], bl[4][2];
#pragma unroll
            for (int p = 0; p < 2; p++) {
                int row = warp_n * 32 + p * 16 + b_lrow;
                int c = cb + b_lchsel;
                unsigned off = row * 128 + (((unsigned)(c ^ (row & 7))) << 4);
                unsigned r4[4];
                ldsm_x4(r4, cur + 32768 + off);
                bh[2 * p][0] = r4[0]; bh[2 * p][1] = r4[1];
                bh[2 * p + 1][0] = r4[2]; bh[2 * p + 1][1] = r4[3];
                ldsm_x4(r4, cur + 40960 + off);
                bl[2 * p][0] = r4[0]; bl[2 * p][1] = r4[1];
                bl[2 * p + 1][0] = r4[2]; bl[2 * p + 1][1] = r4[3];
            }
#pragma unroll
            for (int mi = 0; mi < 2; mi++)
#pragma unroll
                for (int ni = 0; ni < 4; ni++) {
                    mma16816(acc[mi][ni], ah[mi], bl[ni]);
                    mma16816(acc[mi][ni], al_[mi], bh[ni]);
                    mma16816(acc[mi][ni], ah[mi], bh[ni]);
                }
        }
        __syncthreads();
    }

    // epilogue
    int g = lane >> 2, t = lane & 3;
#pragma unroll
    for (int mi = 0; mi < 2; mi++) {
        int r0 = brow + warp_m * 32 + mi * 16 + g;
#pragma unroll
        for (int ni = 0; ni < 4; ni++) {
            int c0 = bcol + warp_n * 32 + ni * 8 + 2 * t;
            float b0 = bias ? bias[c0] : 0.f;
            float b1 = bias ? bias[c0 + 1] : 0.f;
            float v0 = acc[mi][ni][0] + b0;
            float v1 = acc[mi][ni][1] + b1;
            float v2 = acc[mi][ni][2] + b0;
            float v3 = acc[mi][ni][3] + b1;
            __nv_bfloat16 h0, l0, h1, l1;
            __nv_bfloat162 hp, lp;
            dec2(v0, h0, l0); dec2(v1, h1, l1);
            hp.x = h0; hp.y = h1; lp.x = l0; lp.y = l1;
            *(__nv_bfloat162*)&Chi[(long)r0 * Ncols + c0] = hp;
            *(__nv_bfloat162*)&Clo[(long)r0 * Ncols + c0] = lp;
            dec2(v2, h0, l0); dec2(v3, h1, l1);
            hp.x = h0; hp.y = h1; lp.x = l0; lp.y = l1;
            *(__nv_bfloat162*)&Chi[(long)(r0 + 8) * Ncols + c0] = hp;
            *(__nv_bfloat162*)&Clo[(long)(r0 + 8) * Ncols + c0] = lp;
        }
    }
}

// ---------------- per-node attention scalars (bf16 hi+lo) -------------------
__global__ void attn_kernel(const float* __restrict__ att_src,
                            const float* __restrict__ att_dst) {
    int n = blockIdx.x;
    int w = threadIdx.x >> 5, lane = threadIdx.x & 31;
    const __nv_bfloat16* hh = d_hhi + (size_t)n * OUT + w * EMB;
    const __nv_bfloat16* hl = d_hlo + (size_t)n * OUT + w * EMB;
    const float* as = att_src + w * EMB;
    const float* ad = att_dst + w * EMB;
    float s1 = 0.f, s2 = 0.f;
#pragma unroll
    for (int it = 0; it < 2; it++) {
        int c0 = (lane + it * 32) * 8;
        uint4 vh = *(const uint4*)(hh + c0);
        uint4 vl = *(const uint4*)(hl + c0);
        const __nv_bfloat162* ph = (const __nv_bfloat162*)&vh;
        const __nv_bfloat162* pl = (const __nv_bfloat162*)&vl;
#pragma unroll
        for (int j = 0; j < 4; j++) {
            float2 fh = __bfloat1622float2(ph[j]);
            float2 fl = __bfloat1622float2(pl[j]);
            float vx = fh.x + fl.x, vy = fh.y + fl.y;
            float ax = as[c0 + 2 * j], ay = as[c0 + 2 * j + 1];
            float dx = ad[c0 + 2 * j], dy = ad[c0 + 2 * j + 1];
            s1 += vx * ax + vy * ay;
            s2 += vx * dx + vy * dy;
        }
    }
#pragma unroll
    for (int o = 16; o; o >>= 1) {
        s1 += __shfl_down_sync(0xffffffffu, s1, o);
        s2 += __shfl_down_sync(0xffffffffu, s2, o);
    }
    if (lane == 0) { d_asrc[n * 4 + w] = s1; d_adst[n * 4 + w] = s2; }
}

// ---------------- CSR build -------------------------------------------------
__global__ void count_kernel(const int* __restrict__ ei) {
    int e = blockIdx.x * blockDim.x + threadIdx.x;
    if (e >= NTOT) return;
    int dst = (e < NE) ? ei[NE + e] : (e - NE);
    atomicAdd(&d_deg[dst], 1);
}

__global__ void scan_kernel() {
    __shared__ int sh[1024];
    __shared__ int carry;
    int tid = threadIdx.x;
    if (tid == 0) carry = 0;
    __syncthreads();
    for (int ch = 0; ch < N_NODES / 1024; ch++) {
        int i = ch * 1024 + tid;
        int v = d_deg[i];
        sh[tid] = v;
        __syncthreads();
        for (int o = 1; o < 1024; o <<= 1) {
            int x = (tid >= o) ? sh[tid - o] : 0;
            __syncthreads();
            sh[tid] += x;
            __syncthreads();
        }
        int excl = carry + sh[tid] - v;
        d_off[i] = excl;
        d_pos[i] = excl;
        __syncthreads();
        if (tid == 1023) carry += sh[1023];
        __syncthreads();
    }
    if (tid == 0) d_off[N_NODES] = carry;
}

__global__ void scatter_kernel(const int* __restrict__ ei) {
    int e = blockIdx.x * blockDim.x + threadIdx.x;
    if (e >= NTOT) return;
    int dst = (e < NE) ? ei[NE + e] : (e - NE);
    int p = atomicAdd(&d_pos[dst], 1);
    d_eidx[p] = e;
}

// ---------------- softmax passes -------------------------------------------
__global__ void alpha1_kernel(const int* __restrict__ ei) {
    int e = blockIdx.x * blockDim.x + threadIdx.x;
    if (e >= NTOT) return;
    int src, dst;
    if (e < NE) { src = ei[e]; dst = ei[NE + e]; }
    else        { src = dst = e - NE; }
    float4 as = *(const float4*)&d_asrc[src * 4];
    float4 ad = *(const float4*)&d_adst[dst * 4];
    float r[4] = {as.x + ad.x, as.y + ad.y, as.z + ad.z, as.w + ad.w};
#pragma unroll
    for (int h = 0; h < 4; h++) {
        r[h] = r[h] > 0.f ? r[h] : 0.2f * r[h];
        atomicMax(&d_amax[dst * 4 + h], fenc(r[h]));
    }
    *(float4*)&d_alpha[(size_t)e * 4] = make_float4(r[0], r[1], r[2], r[3]);
}

__global__ void alpha2_kernel(const int* __restrict__ ei) {
    int e = blockIdx.x * blockDim.x + threadIdx.x;
    if (e >= NTOT) return;
    int dst = (e < NE) ? ei[NE + e] : (e - NE);
    float4 r = *(const float4*)&d_alpha[(size_t)e * 4];
    float a0 = expf(r.x - fdec(d_amax[dst * 4 + 0]));
    float a1 = expf(r.y - fdec(d_amax[dst * 4 + 1]));
    float a2 = expf(r.z - fdec(d_amax[dst * 4 + 2]));
    float a3 = expf(r.w - fdec(d_amax[dst * 4 + 3]));
    *(float4*)&d_alpha[(size_t)e * 4] = make_float4(a0, a1, a2, a3);
    atomicAdd(&d_denom[dst * 4 + 0], a0);
    atomicAdd(&d_denom[dst * 4 + 1], a1);
    atomicAdd(&d_denom[dst * 4 + 2], a2);
    atomicAdd(&d_denom[dst * 4 + 3], a3);
}

// ---------------- message aggregation (CSR, h = hi + lo, full precision) ----
__global__ void aggregate_kernel(const int* __restrict__ ei,
                                 const float* __restrict__ bias_gat) {
    int dst = blockIdx.x, t = threadIdx.x;  // 256 threads
    int c0 = t * 8;
    int head = c0 >> 9;
    float acc[8] = {0.f, 0.f, 0.f, 0.f, 0.f, 0.f, 0.f, 0.f};
    int s = d_off[dst], e = d_off[dst + 1];
    float dn = d_denom[dst * 4 + head];
    float inv = 1.f / (dn + 1e-16f);
    for (int i = s; i < e; i++) {
        int ed = d_eidx[i];
        int src = (ed < NE) ? ei[ed] : (ed - NE);
        float al = d_alpha[(size_t)ed * 4 + head] * inv;
        size_t base = (size_t)src * OUT + c0;
        uint4 vh = *(const uint4*)(d_hhi + base);
        uint4 vl = *(const uint4*)(d_hlo + base);
        const __nv_bfloat162* ph = (const __nv_bfloat162*)&vh;
        const __nv_bfloat162* pl = (const __nv_bfloat162*)&vl;
#pragma unroll
        for (int j = 0; j < 4; j++) {
            float2 fh = __bfloat1622float2(ph[j]);
            float2 fl = __bfloat1622float2(pl[j]);
            acc[2 * j]     += (fh.x + fl.x) * al;
            acc[2 * j + 1] += (fh.y + fl.y) * al;
        }
    }
    float ob[8];
#pragma unroll
    for (int j = 0; j < 8; j++) {
        float v = acc[j] + bias_gat[c0 + j];
        ob[j] = v > 0.f ? v : 0.01f * v;
    }
    float* op = d_of + (size_t)dst * OUT + c0;
    *(float4*)(op)     = make_float4(ob[0], ob[1], ob[2], ob[3]);
    *(float4*)(op + 4) = make_float4(ob[4], ob[5], ob[6], ob[7]);
}

// ---------------- graph boundaries + pooling --------------------------------
__global__ void gbound_kernel(const int* __restrict__ batch) {
    int i = blockIdx.x * blockDim.x + threadIdx.x;
    if (i >= N_NODES) return;
    atomicMin(&d_gstart[batch[i]], i);
}

__global__ void gfix_kernel() {
    if (threadIdx.x == 0) {
        d_gstart[NB] = N_NODES;
        for (int b = NB - 1; b >= 0; b--)
            if (d_gstart[b] > d_gstart[b + 1]) d_gstart[b] = d_gstart[b + 1];
    }
}

__global__ void pool_kernel() {  // grid (16, NB), 128 threads
    int b = blockIdx.y;
    int c = blockIdx.x * 128 + threadIdx.x;
    int s = d_gstart[b], e = d_gstart[b + 1];
    float sum = 0.f, mx = -INFINITY;
    for (int i = s; i < e; i++) {
        float v = d_of[(size_t)i * OUT + c];
        sum += v;
        mx = fmaxf(mx, v);
    }
    float cnt = (float)(e - s);
    d_g[b * 2 * OUT + c] = sum / fmaxf(cnt, 1.f);
    d_g[b * 2 * OUT + OUT + c] = mx;
}

// ---------------- head MLPs -------------------------------------------------
__global__ void mlp_kernel(const float* __restrict__ W1r, const float* __restrict__ b1r,
                           const float* __restrict__ W2r, const float* __restrict__ b2r,
                           const float* __restrict__ W1m, const float* __restrict__ b1m,
                           const float* __restrict__ W2m, const float* __restrict__ b2m,
                           float* __restrict__ out) {
    int b = blockIdx.x, task = blockIdx.y;
    const float* W1 = task ? W1m : W1r;
    const float* b1 = task ? b1m : b1r;
    const float* W2 = task ? W2m : W2r;
    const float* b2 = task ? b2m : b2r;
    __shared__ float gs[2 * OUT];
    __shared__ float part[128];
    int t = threadIdx.x;
    for (int k = t; k < 2 * OUT; k += 128) gs[k] = d_g[b * 2 * OUT + k];
    __syncthreads();
    int j = t & 31, seg = t >> 5;
    float s = 0.f;
    for (int k = seg; k < 2 * OUT; k += 4) s += gs[k] * W1[k * HID + j];
    part[t] = s;
    __syncthreads();
    if (t < 32) {
        float hj = part[t] + part[t + 32] + part[t + 64] + part[t + 96] + b1[t];
        hj = fmaxf(hj, 0.f);
        float p = hj * W2[t];
#pragma unroll
        for (int o = 16; o; o >>= 1) p += __shfl_down_sync(0xffffffffu, p, o);
        if (t == 0) out[task * NB + b] = p + b2[0];
    }
}

// ---------------- launch ----------------------------------------------------
extern "C" void kernel_launch(void* const* d_in, const int* in_sizes, int n_in,
                              void* d_out, int out_size) {
    const int*   code     = (const int*)d_in[0];
    const int*   ei       = (const int*)d_in[1];
    const int*   batch    = (const int*)d_in[2];
    const float* emb      = (const float*)d_in[3];
    const float* W_feat   = (const float*)d_in[4];
    const float* b_feat   = (const float*)d_in[5];
    const float* W_gat    = (const float*)d_in[6];
    const float* att_src  = (const float*)d_in[7];
    const float* att_dst  = (const float*)d_in[8];
    const float* bias_gat = (const float*)d_in[9];
    const float* W1r = (const float*)d_in[10];
    const float* b1r = (const float*)d_in[11];
    const float* W2r = (const float*)d_in[12];
    const float* b2r = (const float*)d_in[13];
    const float* W1m = (const float*)d_in[14];
    const float* b1m = (const float*)d_in[15];
    const float* W2m = (const float*)d_in[16];
    const float* b2m = (const float*)d_in[17];
    float* out = (float*)d_out;

    static int attr_done = 0;
    if (!attr_done) {
        cudaFuncSetAttribute(gemm_fast_kernel,
                             cudaFuncAttributeMaxDynamicSharedMemorySize, GEMM_SMEM);
        attr_done = 1;
    }

    void *p0, *p1, *p2, *p3, *p4, *p5, *p6, *p7, *p8, *p9;
    cudaGetSymbolAddress(&p0, d_xehi);
    cudaGetSymbolAddress(&p1, d_xelo);
    cudaGetSymbolAddress(&p2, d_xhi);
    cudaGetSymbolAddress(&p3, d_xlo);
    cudaGetSymbolAddress(&p4, d_hhi);
    cudaGetSymbolAddress(&p5, d_hlo);
    cudaGetSymbolAddress(&p6, d_wfhi);
    cudaGetSymbolAddress(&p7, d_wflo);
    cudaGetSymbolAddress(&p8, d_wghi);
    cudaGetSymbolAddress(&p9, d_wglo);
    __nv_bfloat16* xehi = (__nv_bfloat16*)p0;
    __nv_bfloat16* xelo = (__nv_bfloat16*)p1;
    __nv_bfloat16* xhi  = (__nv_bfloat16*)p2;
    __nv_bfloat16* xlo  = (__nv_bfloat16*)p3;
    __nv_bfloat16* hhi  = (__nv_bfloat16*)p4;
    __nv_bfloat16* hlo  = (__nv_bfloat16*)p5;
    __nv_bfloat16* wfhi = (__nv_bfloat16*)p6;
    __nv_bfloat16* wflo = (__nv_bfloat16*)p7;
    __nv_bfloat16* wghi = (__nv_bfloat16*)p8;
    __nv_bfloat16* wglo = (__nv_bfloat16*)p9;

    init_kernel<<<(N_NODES * HEADS + 255) / 256, 256>>>();

    prepW_kernel<<<dim3(EMB / 32, EMB / 32), 256>>>(W_feat, EMB, EMB, wfhi, wflo);
    prepW_kernel<<<dim3(OUT / 32, EMB / 32), 256>>>(W_gat, EMB, OUT, wghi, wglo);
    gathdec_kernel<<<(N_NODES * EMB / 4) / 256, 256>>>(emb, code);

    // x = emb[code] @ W_feat + b_feat  -> bf16 hi/lo
    gemm_fast_kernel<<<dim3(EMB / BN, N_NODES / BM), 256, GEMM_SMEM>>>(
        xehi, xelo, wfhi, wflo, b_feat, xhi, xlo, EMB, EMB);
    // h = x @ W_gat -> bf16 hi/lo
    gemm_fast_kernel<<<dim3(OUT / BN, N_NODES / BM), 256, GEMM_SMEM>>>(
        xhi, xlo, wghi, wglo, nullptr, hhi, hlo, EMB, OUT);

    attn_kernel<<<N_NODES, 128>>>(att_src, att_dst);

    count_kernel<<<(NTOT + 255) / 256, 256>>>(ei);
    scan_kernel<<<1, 1024>>>();
    scatter_kernel<<<(NTOT + 255) / 256, 256>>>(ei);

    alpha1_kernel<<<(NTOT + 255) / 256, 256>>>(ei);
    alpha2_kernel<<<(NTOT + 255) / 256, 256>>>(ei);

    aggregate_kernel<<<N_NODES, 256>>>(ei, bias_gat);

    gbound_kernel<<<(N_NODES + 255) / 256, 256>>>(batch);
    gfix_kernel<<<1, 32>>>();
    pool_kernel<<<dim3(OUT / 128, NB), 128>>>();

    mlp_kernel<<<dim3(NB, 2), 128>>>(W1r, b1r, W2r, b2r, W1m, b1m, W2m, b2m, out);
}

// round 6
// speedup vs baseline: 2.6100x; 1.1834x over previous
#include <cuda_runtime.h>
#include <cuda_bf16.h>
#include <math.h>

#define N_NODES 32768
#define EMB 512
#define HEADS 4
#define OUT 2048
#define NE 131072
#define NTOT (NE + N_NODES)
#define NB 32
#define HID 32

#define BM 128
#define BN 64
#define BKC 64            // k-chunk (bf16 elems) = 128 bytes/row
#define GEMM_STAGE_BYTES 49152   // (128+128+64+64)*128 bytes
#define GEMM_SMEM (2 * GEMM_STAGE_BYTES)

// ---------------- scratch (static device globals) ---------------------------
__device__ __nv_bfloat16 d_xehi[(size_t)N_NODES * EMB];  // gathered emb hi
__device__ __nv_bfloat16 d_xelo[(size_t)N_NODES * EMB];
__device__ float    d_x[(size_t)N_NODES * EMB];          // after feat linear (fp32)
__device__ __nv_bfloat16 d_zhi[(size_t)N_NODES * OUT];   // aggregated x per head
__device__ __nv_bfloat16 d_zlo[(size_t)N_NODES * OUT];
__device__ float    d_of[(size_t)N_NODES * OUT];         // GAT out (post act)
__device__ __nv_bfloat16 d_wfhi[(size_t)EMB * EMB];
__device__ __nv_bfloat16 d_wflo[(size_t)EMB * EMB];
__device__ __nv_bfloat16 d_wghi[(size_t)OUT * EMB];
__device__ __nv_bfloat16 d_wglo[(size_t)OUT * EMB];
__device__ float    d_wt[8 * EMB];                       // folded att vectors
__device__ float    d_asrc[N_NODES * HEADS];
__device__ float    d_adst[N_NODES * HEADS];
__device__ float    d_alpha[(size_t)NTOT * HEADS];
__device__ unsigned d_amax[N_NODES * HEADS];
__device__ float    d_denom[N_NODES * HEADS];
__device__ int      d_deg[N_NODES];
__device__ int      d_off[N_NODES + 1];
__device__ int      d_pos[N_NODES];
__device__ int      d_eidx[NTOT];
__device__ float    d_g[NB * 2 * OUT];
__device__ int      d_gstart[NB + 1];

__device__ __forceinline__ unsigned fenc(float f) {
    unsigned u = __float_as_uint(f);
    return (u >> 31) ? ~u : (u | 0x80000000u);
}
__device__ __forceinline__ float fdec(unsigned u) {
    u = (u >> 31) ? (u & 0x7fffffffu) : ~u;
    return __uint_as_float(u);
}
__device__ __forceinline__ void dec2(float v, __nv_bfloat16& h, __nv_bfloat16& l) {
    h = __float2bfloat16_rn(v);
    l = __float2bfloat16_rn(v - __bfloat162float(h));
}
__device__ __forceinline__ void mma16816(float* c, const unsigned* a, const unsigned* b) {
    asm volatile(
        "mma.sync.aligned.m16n8k16.row.col.f32.bf16.bf16.f32 "
        "{%0,%1,%2,%3}, {%4,%5,%6,%7}, {%8,%9}, {%0,%1,%2,%3};"
        : "+f"(c[0]), "+f"(c[1]), "+f"(c[2]), "+f"(c[3])
        : "r"(a[0]), "r"(a[1]), "r"(a[2]), "r"(a[3]), "r"(b[0]), "r"(b[1]));
}
__device__ __forceinline__ void ldsm_x4(unsigned* r, unsigned addr) {
    asm volatile("ldmatrix.sync.aligned.m8n8.x4.shared.b16 {%0,%1,%2,%3}, [%4];"
                 : "=r"(r[0]), "=r"(r[1]), "=r"(r[2]), "=r"(r[3]) : "r"(addr));
}
__device__ __forceinline__ void cpasync16(unsigned saddr, const void* gaddr) {
    asm volatile("cp.async.cg.shared.global [%0], [%1], 16;" :: "r"(saddr), "l"(gaddr));
}
__device__ __forceinline__ void cpcommit() { asm volatile("cp.async.commit_group;"); }
__device__ __forceinline__ void cpwaitall() { asm volatile("cp.async.wait_group 0;"); }

// ---------------- init ------------------------------------------------------
__global__ void init_kernel() {
    int i = blockIdx.x * blockDim.x + threadIdx.x;
    if (i < N_NODES * HEADS) { d_amax[i] = 0u; d_denom[i] = 0.f; }
    if (i < N_NODES) d_deg[i] = 0;
    if (i <= NB) d_gstart[i] = N_NODES;
}

// ---------------- weight prep: transpose fp32 [K][N] -> bf16 hi/lo [N][K] ---
__global__ void prepW_kernel(const float* __restrict__ W, int K, int N,
                             __nv_bfloat16* __restrict__ Whi,
                             __nv_bfloat16* __restrict__ Wlo) {
    __shared__ float tile[32][33];
    int kx = blockIdx.y * 32, nx = blockIdx.x * 32;
    int tx = threadIdx.x & 31, ty = threadIdx.x >> 5;
#pragma unroll
    for (int p = 0; p < 4; p++)
        tile[ty + p * 8][tx] = W[(long)(kx + ty + p * 8) * N + nx + tx];
    __syncthreads();
#pragma unroll
    for (int p = 0; p < 4; p++) {
        int nl = ty + p * 8, kl = tx;
        float v = tile[kl][nl];
        __nv_bfloat16 h, l;
        dec2(v, h, l);
        long o = (long)(nx + nl) * K + kx + kl;
        Whi[o] = h;
        Wlo[o] = l;
    }
}

// ---------------- fold att vectors through W_gat: wt[q][k] ------------------
// wt[q=which*4+hd][k] = sum_c W_gat[k][hd*512+c] * att[hd][c]
__global__ void prepwt_kernel(const float* __restrict__ W_gat,
                              const float* __restrict__ att_src,
                              const float* __restrict__ att_dst) {
    int k = blockIdx.x;
    int w = threadIdx.x >> 5, lane = threadIdx.x & 31;
    int hd = w & 3;
    const float* att = (w < 4) ? att_src : att_dst;
    const float* wr = W_gat + (long)k * OUT + hd * EMB;
    const float* ar = att + hd * EMB;
    float s = 0.f;
    for (int c = lane; c < EMB; c += 32) s += wr[c] * ar[c];
#pragma unroll
    for (int o = 16; o; o >>= 1) s += __shfl_down_sync(0xffffffffu, s, o);
    if (lane == 0) d_wt[w * EMB + k] = s;
}

// ---------------- gather emb rows + decompose to bf16 hi/lo -----------------
__global__ void gathdec_kernel(const float* __restrict__ emb,
                               const int* __restrict__ code) {
    long i = (long)blockIdx.x * blockDim.x + threadIdx.x;  // N*EMB/4 threads
    int row = (int)(i >> 7);
    int c4 = (int)(i & 127) * 4;
    float4 v = *(const float4*)(emb + (long)code[row] * EMB + c4);
    __nv_bfloat16 h0, l0, h1, l1, h2, l2, h3, l3;
    dec2(v.x, h0, l0); dec2(v.y, h1, l1);
    dec2(v.z, h2, l2); dec2(v.w, h3, l3);
    long o = (long)row * EMB + c4;
    __nv_bfloat162 p;
    p.x = h0; p.y = h1; *(__nv_bfloat162*)&d_xehi[o] = p;
    p.x = h2; p.y = h3; *(__nv_bfloat162*)&d_xehi[o + 2] = p;
    p.x = l0; p.y = l1; *(__nv_bfloat162*)&d_xelo[o] = p;
    p.x = l2; p.y = l3; *(__nv_bfloat162*)&d_xelo[o + 2] = p;
}

// ---------------- bf16x3 tensor-core GEMM (cp.async + ldmatrix) -------------
// C[r][c] = sum_k A[r][k]*B[c][k] + bias[c]; fp32 output, optional leaky 0.01.
// blockIdx.z offsets (for per-head block-diagonal GEMM).
template <bool LEAKY>
__global__ void __launch_bounds__(256, 2) gemm_fast_kernel(
    const __nv_bfloat16* __restrict__ Ahi, const __nv_bfloat16* __restrict__ Alo,
    int lda,
    const __nv_bfloat16* __restrict__ Bhi, const __nv_bfloat16* __restrict__ Blo,
    const float* __restrict__ bias,
    float* __restrict__ C, int ldc,
    int K, long zsA, long zsB, int zsBias, int zsC) {
    extern __shared__ char smem[];
    unsigned sbase = (unsigned)__cvta_generic_to_shared(smem);

    int hz = blockIdx.z;
    Ahi += (long)hz * zsA; Alo += (long)hz * zsA;
    Bhi += (long)hz * zsB; Blo += (long)hz * zsB;
    bias += hz * zsBias;
    C += (long)hz * zsC;

    int tid = threadIdx.x;
    int wid = tid >> 5, lane = tid & 31;
    int warp_m = wid >> 1, warp_n = wid & 1;
    int brow = blockIdx.y * BM, bcol = blockIdx.x * BN;

    const __nv_bfloat16 *agp_h[4], *agp_l[4], *bgp_h[2], *bgp_l[2];
    unsigned asm_h[4], asm_l[4], bsm_h[2], bsm_l[2];
#pragma unroll
    for (int p = 0; p < 4; p++) {
        int id = tid + 256 * p;
        int ar = id >> 3, ac = id & 7;
        agp_h[p] = Ahi + (long)(brow + ar) * lda + ac * 8;
        agp_l[p] = Alo + (long)(brow + ar) * lda + ac * 8;
        unsigned so = ar * 128 + ((ac ^ (ar & 7)) << 4);
        asm_h[p] = so;
        asm_l[p] = 16384 + so;
    }
#pragma unroll
    for (int p = 0; p < 2; p++) {
        int id = tid + 256 * p;
        int br = id >> 3, bc = id & 7;
        bgp_h[p] = Bhi + (long)(bcol + br) * K + bc * 8;
        bgp_l[p] = Blo + (long)(bcol + br) * K + bc * 8;
        unsigned so = br * 128 + ((bc ^ (br & 7)) << 4);
        bsm_h[p] = 32768 + so;
        bsm_l[p] = 40960 + so;
    }

    float acc[2][4][4];
#pragma unroll
    for (int mi = 0; mi < 2; mi++)
#pragma unroll
        for (int ni = 0; ni < 4; ni++)
#pragma unroll
            for (int j = 0; j < 4; j++) acc[mi][ni][j] = 0.f;

    int nch = K / BKC;
    {
        unsigned sb = sbase;
#pragma unroll
        for (int p = 0; p < 4; p++) {
            cpasync16(sb + asm_h[p], agp_h[p]);
            cpasync16(sb + asm_l[p], agp_l[p]);
        }
#pragma unroll
        for (int p = 0; p < 2; p++) {
            cpasync16(sb + bsm_h[p], bgp_h[p]);
            cpasync16(sb + bsm_l[p], bgp_l[p]);
        }
        cpcommit();
    }

    int a_lrow = (lane & 15);
    int a_lchsel = (lane >> 4);
    int b_lrow = (lane & 7) + ((lane >> 4) << 3);
    int b_lchsel = (lane >> 3) & 1;

    for (int ch = 0; ch < nch; ch++) {
        cpwaitall();
        __syncthreads();
        unsigned cur = sbase + (unsigned)(ch & 1) * GEMM_STAGE_BYTES;
        if (ch + 1 < nch) {
            unsigned nxt = sbase + (unsigned)((ch + 1) & 1) * GEMM_STAGE_BYTES;
            int kk = (ch + 1) * BKC;
#pragma unroll
            for (int p = 0; p < 4; p++) {
                cpasync16(nxt + asm_h[p], agp_h[p] + kk);
                cpasync16(nxt + asm_l[p], agp_l[p] + kk);
            }
#pragma unroll
            for (int p = 0; p < 2; p++) {
                cpasync16(nxt + bsm_h[p], bgp_h[p] + kk);
                cpasync16(nxt + bsm_l[p], bgp_l[p] + kk);
            }
            cpcommit();
        }

#pragma unroll
        for (int ks = 0; ks < 4; ks++) {
            int cb = ks << 1;
            unsigned ah[2][4], al_[2][4];
#pragma unroll
            for (int mi = 0; mi < 2; mi++) {
                int row = warp_m * 32 + mi * 16 + a_lrow;
                int c = cb + a_lchsel;
                unsigned off = row * 128 + (((unsigned)(c ^ (row & 7))) << 4);
                ldsm_x4(ah[mi], cur + off);
                ldsm_x4(al_[mi], cur + 16384 + off);
            }
            unsigned bh[4][2], bl[4][2];
#pragma unroll
            for (int p = 0; p < 2; p++) {
                int row = warp_n * 32 + p * 16 + b_lrow;
                int c = cb + b_lchsel;
                unsigned off = row * 128 + (((unsigned)(c ^ (row & 7))) << 4);
                unsigned r4[4];
                ldsm_x4(r4, cur + 32768 + off);
                bh[2 * p][0] = r4[0]; bh[2 * p][1] = r4[1];
                bh[2 * p + 1][0] = r4[2]; bh[2 * p + 1][1] = r4[3];
                ldsm_x4(r4, cur + 40960 + off);
                bl[2 * p][0] = r4[0]; bl[2 * p][1] = r4[1];
                bl[2 * p + 1][0] = r4[2]; bl[2 * p + 1][1] = r4[3];
            }
#pragma unroll
            for (int mi = 0; mi < 2; mi++)
#pragma unroll
                for (int ni = 0; ni < 4; ni++) {
                    mma16816(acc[mi][ni], ah[mi], bl[ni]);
                    mma16816(acc[mi][ni], al_[mi], bh[ni]);
                    mma16816(acc[mi][ni], ah[mi], bh[ni]);
                }
        }
        __syncthreads();
    }

    int g = lane >> 2, t = lane & 3;
#pragma unroll
    for (int mi = 0; mi < 2; mi++) {
        int r0 = brow + warp_m * 32 + mi * 16 + g;
#pragma unroll
        for (int ni = 0; ni < 4; ni++) {
            int c0 = bcol + warp_n * 32 + ni * 8 + 2 * t;
            float b0 = bias[c0], b1 = bias[c0 + 1];
            float v0 = acc[mi][ni][0] + b0;
            float v1 = acc[mi][ni][1] + b1;
            float v2 = acc[mi][ni][2] + b0;
            float v3 = acc[mi][ni][3] + b1;
            if (LEAKY) {
                v0 = v0 > 0.f ? v0 : 0.01f * v0;
                v1 = v1 > 0.f ? v1 : 0.01f * v1;
                v2 = v2 > 0.f ? v2 : 0.01f * v2;
                v3 = v3 > 0.f ? v3 : 0.01f * v3;
            }
            *(float2*)&C[(long)r0 * ldc + c0] = make_float2(v0, v1);
            *(float2*)&C[(long)(r0 + 8) * ldc + c0] = make_float2(v2, v3);
        }
    }
}

// ---------------- attention scalars from x and folded wt --------------------
__global__ void attnx_kernel() {
    __shared__ float wt[8 * EMB];
    int tid = threadIdx.x;  // 256
    for (int i = tid; i < 8 * EMB; i += 256) wt[i] = d_wt[i];
    __syncthreads();
    int w = tid >> 5, lane = tid & 31;
    int n = blockIdx.x * 8 + w;
    const float* xr = d_x + (size_t)n * EMB;
    float s[8] = {0.f, 0.f, 0.f, 0.f, 0.f, 0.f, 0.f, 0.f};
#pragma unroll
    for (int i = 0; i < EMB / 32; i++) {
        float xv = xr[lane + 32 * i];
#pragma unroll
        for (int q = 0; q < 8; q++) s[q] += xv * wt[q * EMB + lane + 32 * i];
    }
#pragma unroll
    for (int o = 16; o; o >>= 1)
#pragma unroll
        for (int q = 0; q < 8; q++) s[q] += __shfl_down_sync(0xffffffffu, s[q], o);
    if (lane == 0) {
        *(float4*)&d_asrc[n * 4] = make_float4(s[0], s[1], s[2], s[3]);
        *(float4*)&d_adst[n * 4] = make_float4(s[4], s[5], s[6], s[7]);
    }
}

// ---------------- CSR build -------------------------------------------------
__global__ void count_kernel(const int* __restrict__ ei) {
    int e = blockIdx.x * blockDim.x + threadIdx.x;
    if (e >= NTOT) return;
    int dst = (e < NE) ? ei[NE + e] : (e - NE);
    atomicAdd(&d_deg[dst], 1);
}

__global__ void scan_kernel() {
    __shared__ int sh[1024];
    __shared__ int carry;
    int tid = threadIdx.x;
    if (tid == 0) carry = 0;
    __syncthreads();
    for (int ch = 0; ch < N_NODES / 1024; ch++) {
        int i = ch * 1024 + tid;
        int v = d_deg[i];
        sh[tid] = v;
        __syncthreads();
        for (int o = 1; o < 1024; o <<= 1) {
            int x = (tid >= o) ? sh[tid - o] : 0;
            __syncthreads();
            sh[tid] += x;
            __syncthreads();
        }
        int excl = carry + sh[tid] - v;
        d_off[i] = excl;
        d_pos[i] = excl;
        __syncthreads();
        if (tid == 1023) carry += sh[1023];
        __syncthreads();
    }
    if (tid == 0) d_off[N_NODES] = carry;
}

__global__ void scatter_kernel(const int* __restrict__ ei) {
    int e = blockIdx.x * blockDim.x + threadIdx.x;
    if (e >= NTOT) return;
    int dst = (e < NE) ? ei[NE + e] : (e - NE);
    int p = atomicAdd(&d_pos[dst], 1);
    d_eidx[p] = e;
}

// ---------------- softmax passes -------------------------------------------
__global__ void alpha1_kernel(const int* __restrict__ ei) {
    int e = blockIdx.x * blockDim.x + threadIdx.x;
    if (e >= NTOT) return;
    int src, dst;
    if (e < NE) { src = ei[e]; dst = ei[NE + e]; }
    else        { src = dst = e - NE; }
    float4 as = *(const float4*)&d_asrc[src * 4];
    float4 ad = *(const float4*)&d_adst[dst * 4];
    float r[4] = {as.x + ad.x, as.y + ad.y, as.z + ad.z, as.w + ad.w};
#pragma unroll
    for (int h = 0; h < 4; h++) {
        r[h] = r[h] > 0.f ? r[h] : 0.2f * r[h];
        atomicMax(&d_amax[dst * 4 + h], fenc(r[h]));
    }
    *(float4*)&d_alpha[(size_t)e * 4] = make_float4(r[0], r[1], r[2], r[3]);
}

__global__ void alpha2_kernel(const int* __restrict__ ei) {
    int e = blockIdx.x * blockDim.x + threadIdx.x;
    if (e >= NTOT) return;
    int dst = (e < NE) ? ei[NE + e] : (e - NE);
    float4 r = *(const float4*)&d_alpha[(size_t)e * 4];
    float a0 = expf(r.x - fdec(d_amax[dst * 4 + 0]));
    float a1 = expf(r.y - fdec(d_amax[dst * 4 + 1]));
    float a2 = expf(r.z - fdec(d_amax[dst * 4 + 2]));
    float a3 = expf(r.w - fdec(d_amax[dst * 4 + 3]));
    *(float4*)&d_alpha[(size_t)e * 4] = make_float4(a0, a1, a2, a3);
    atomicAdd(&d_denom[dst * 4 + 0], a0);
    atomicAdd(&d_denom[dst * 4 + 1], a1);
    atomicAdd(&d_denom[dst * 4 + 2], a2);
    atomicAdd(&d_denom[dst * 4 + 3], a3);
}

// ---------------- aggregation in x-space: z[dst,hd,:] = sum alpha*x[src] ----
__global__ void aggregate_kernel(const int* __restrict__ ei) {
    int dst = blockIdx.x, t = threadIdx.x;  // 256 threads, 2 channels each
    int c = t * 2;
    float acc[4][2] = {{0.f, 0.f}, {0.f, 0.f}, {0.f, 0.f}, {0.f, 0.f}};
    int s = d_off[dst], e = d_off[dst + 1];
    float4 dn = *(const float4*)&d_denom[dst * 4];
    float inv0 = 1.f / (dn.x + 1e-16f);
    float inv1 = 1.f / (dn.y + 1e-16f);
    float inv2 = 1.f / (dn.z + 1e-16f);
    float inv3 = 1.f / (dn.w + 1e-16f);
    for (int i = s; i < e; i++) {
        int ed = d_eidx[i];
        int src = (ed < NE) ? ei[ed] : (ed - NE);
        float4 al = *(const float4*)&d_alpha[(size_t)ed * 4];
        float a0 = al.x * inv0, a1 = al.y * inv1, a2 = al.z * inv2, a3 = al.w * inv3;
        float2 xv = *(const float2*)(d_x + (size_t)src * EMB + c);
        acc[0][0] += a0 * xv.x; acc[0][1] += a0 * xv.y;
        acc[1][0] += a1 * xv.x; acc[1][1] += a1 * xv.y;
        acc[2][0] += a2 * xv.x; acc[2][1] += a2 * xv.y;
        acc[3][0] += a3 * xv.x; acc[3][1] += a3 * xv.y;
    }
#pragma unroll
    for (int hd = 0; hd < 4; hd++) {
        __nv_bfloat16 h0, l0, h1, l1;
        dec2(acc[hd][0], h0, l0);
        dec2(acc[hd][1], h1, l1);
        size_t o = ((size_t)dst * 4 + hd) * EMB + c;
        __nv_bfloat162 hp, lp;
        hp.x = h0; hp.y = h1; lp.x = l0; lp.y = l1;
        *(__nv_bfloat162*)&d_zhi[o] = hp;
        *(__nv_bfloat162*)&d_zlo[o] = lp;
    }
}

// ---------------- graph boundaries + pooling --------------------------------
__global__ void gbound_kernel(const int* __restrict__ batch) {
    int i = blockIdx.x * blockDim.x + threadIdx.x;
    if (i >= N_NODES) return;
    atomicMin(&d_gstart[batch[i]], i);
}

__global__ void gfix_kernel() {
    if (threadIdx.x == 0) {
        d_gstart[NB] = N_NODES;
        for (int b = NB - 1; b >= 0; b--)
            if (d_gstart[b] > d_gstart[b + 1]) d_gstart[b] = d_gstart[b + 1];
    }
}

__global__ void pool_kernel() {  // grid (16, NB), 128 threads
    int b = blockIdx.y;
    int c = blockIdx.x * 128 + threadIdx.x;
    int s = d_gstart[b], e = d_gstart[b + 1];
    float sum = 0.f, mx = -INFINITY;
    for (int i = s; i < e; i++) {
        float v = d_of[(size_t)i * OUT + c];
        sum += v;
        mx = fmaxf(mx, v);
    }
    float cnt = (float)(e - s);
    d_g[b * 2 * OUT + c] = sum / fmaxf(cnt, 1.f);
    d_g[b * 2 * OUT + OUT + c] = mx;
}

// ---------------- head MLPs -------------------------------------------------
__global__ void mlp_kernel(const float* __restrict__ W1r, const float* __restrict__ b1r,
                           const float* __restrict__ W2r, const float* __restrict__ b2r,
                           const float* __restrict__ W1m, const float* __restrict__ b1m,
                           const float* __restrict__ W2m, const float* __restrict__ b2m,
                           float* __restrict__ out) {
    int b = blockIdx.x, task = blockIdx.y;
    const float* W1 = task ? W1m : W1r;
    const float* b1 = task ? b1m : b1r;
    const float* W2 = task ? W2m : W2r;
    const float* b2 = task ? b2m : b2r;
    __shared__ float gs[2 * OUT];
    __shared__ float part[128];
    int t = threadIdx.x;
    for (int k = t; k < 2 * OUT; k += 128) gs[k] = d_g[b * 2 * OUT + k];
    __syncthreads();
    int j = t & 31, seg = t >> 5;
    float s = 0.f;
    for (int k = seg; k < 2 * OUT; k += 4) s += gs[k] * W1[k * HID + j];
    part[t] = s;
    __syncthreads();
    if (t < 32) {
        float hj = part[t] + part[t + 32] + part[t + 64] + part[t + 96] + b1[t];
        hj = fmaxf(hj, 0.f);
        float p = hj * W2[t];
#pragma unroll
        for (int o = 16; o; o >>= 1) p += __shfl_down_sync(0xffffffffu, p, o);
        if (t == 0) out[task * NB + b] = p + b2[0];
    }
}

// ---------------- launch ----------------------------------------------------
extern "C" void kernel_launch(void* const* d_in, const int* in_sizes, int n_in,
                              void* d_out, int out_size) {
    const int*   code     = (const int*)d_in[0];
    const int*   ei       = (const int*)d_in[1];
    const int*   batch    = (const int*)d_in[2];
    const float* emb      = (const float*)d_in[3];
    const float* W_feat   = (const float*)d_in[4];
    const float* b_feat   = (const float*)d_in[5];
    const float* W_gat    = (const float*)d_in[6];
    const float* att_src  = (const float*)d_in[7];
    const float* att_dst  = (const float*)d_in[8];
    const float* bias_gat = (const float*)d_in[9];
    const float* W1r = (const float*)d_in[10];
    const float* b1r = (const float*)d_in[11];
    const float* W2r = (const float*)d_in[12];
    const float* b2r = (const float*)d_in[13];
    const float* W1m = (const float*)d_in[14];
    const float* b1m = (const float*)d_in[15];
    const float* W2m = (const float*)d_in[16];
    const float* b2m = (const float*)d_in[17];
    float* out = (float*)d_out;

    static int attr_done = 0;
    if (!attr_done) {
        cudaFuncSetAttribute(gemm_fast_kernel<false>,
                             cudaFuncAttributeMaxDynamicSharedMemorySize, GEMM_SMEM);
        cudaFuncSetAttribute(gemm_fast_kernel<true>,
                             cudaFuncAttributeMaxDynamicSharedMemorySize, GEMM_SMEM);
        attr_done = 1;
    }

    void *p0, *p1, *p2, *p3, *p4, *p5, *p6, *p7, *p8, *p9;
    cudaGetSymbolAddress(&p0, d_xehi);
    cudaGetSymbolAddress(&p1, d_xelo);
    cudaGetSymbolAddress(&p2, d_x);
    cudaGetSymbolAddress(&p3, d_zhi);
    cudaGetSymbolAddress(&p4, d_zlo);
    cudaGetSymbolAddress(&p5, d_of);
    cudaGetSymbolAddress(&p6, d_wfhi);
    cudaGetSymbolAddress(&p7, d_wflo);
    cudaGetSymbolAddress(&p8, d_wghi);
    cudaGetSymbolAddress(&p9, d_wglo);
    __nv_bfloat16* xehi = (__nv_bfloat16*)p0;
    __nv_bfloat16* xelo = (__nv_bfloat16*)p1;
    float*         xp   = (float*)p2;
    __nv_bfloat16* zhi  = (__nv_bfloat16*)p3;
    __nv_bfloat16* zlo  = (__nv_bfloat16*)p4;
    float*         ofp  = (float*)p5;
    __nv_bfloat16* wfhi = (__nv_bfloat16*)p6;
    __nv_bfloat16* wflo = (__nv_bfloat16*)p7;
    __nv_bfloat16* wghi = (__nv_bfloat16*)p8;
    __nv_bfloat16* wglo = (__nv_bfloat16*)p9;

    init_kernel<<<(N_NODES * HEADS + 255) / 256, 256>>>();

    prepW_kernel<<<dim3(EMB / 32, EMB / 32), 256>>>(W_feat, EMB, EMB, wfhi, wflo);
    prepW_kernel<<<dim3(OUT / 32, EMB / 32), 256>>>(W_gat, EMB, OUT, wghi, wglo);
    prepwt_kernel<<<EMB, 256>>>(W_gat, att_src, att_dst);
    gathdec_kernel<<<(N_NODES * EMB / 4) / 256, 256>>>(emb, code);

    // x = emb[code] @ W_feat + b_feat  -> fp32
    gemm_fast_kernel<false><<<dim3(EMB / BN, N_NODES / BM, 1), 256, GEMM_SMEM>>>(
        xehi, xelo, EMB, wfhi, wflo, b_feat, xp, EMB, EMB, 0, 0, 0, 0);

    attnx_kernel<<<N_NODES / 8, 256>>>();

    count_kernel<<<(NTOT + 255) / 256, 256>>>(ei);
    scan_kernel<<<1, 1024>>>();
    scatter_kernel<<<(NTOT + 255) / 256, 256>>>(ei);

    alpha1_kernel<<<(NTOT + 255) / 256, 256>>>(ei);
    alpha2_kernel<<<(NTOT + 255) / 256, 256>>>(ei);

    aggregate_kernel<<<N_NODES, 256>>>(ei);

    // of[:, hd*512:...] = z[:, hd, :] @ Wg_hd + bias_gat, leaky 0.01 (fused)
    gemm_fast_kernel<true><<<dim3(EMB / BN, N_NODES / BM, HEADS), 256, GEMM_SMEM>>>(
        zhi, zlo, OUT, wghi, wglo, bias_gat, ofp, OUT,
        EMB, (long)EMB, (long)EMB * EMB, EMB, EMB);

    gbound_kernel<<<(N_NODES + 255) / 256, 256>>>(batch);
    gfix_kernel<<<1, 32>>>();
    pool_kernel<<<dim3(OUT / 128, NB), 128>>>();

    mlp_kernel<<<dim3(NB, 2), 128>>>(W1r, b1r, W2r, b2r, W1m, b1m, W2m, b2m, out);
}

// round 7
// speedup vs baseline: 2.8015x; 1.0733x over previous
#include <cuda_runtime.h>
#include <cuda_bf16.h>
#include <math.h>

#define N_NODES 32768
#define EMB 512
#define HEADS 4
#define OUT 2048
#define NE 131072
#define NTOT (NE + N_NODES)
#define NB 32
#define HID 32

#define BM 128
#define BN 64
#define BKC 64            // k-chunk (bf16 elems) = 128 bytes/row
#define GEMM_STAGE_BYTES 49152   // (128+128+64+64)*128 bytes
#define GEMM_SMEM (2 * GEMM_STAGE_BYTES)

// ---------------- scratch (static device globals) ---------------------------
__device__ __nv_bfloat16 d_xehi[(size_t)N_NODES * EMB];  // gathered emb hi
__device__ __nv_bfloat16 d_xelo[(size_t)N_NODES * EMB];
__device__ float    d_x[(size_t)N_NODES * EMB];          // after feat linear (fp32)
__device__ __nv_bfloat16 d_zhi[(size_t)N_NODES * OUT];   // aggregated x per head
__device__ __nv_bfloat16 d_zlo[(size_t)N_NODES * OUT];
__device__ __nv_bfloat16 d_wfhi[(size_t)EMB * EMB];
__device__ __nv_bfloat16 d_wflo[(size_t)EMB * EMB];
__device__ __nv_bfloat16 d_wghi[(size_t)OUT * EMB];
__device__ __nv_bfloat16 d_wglo[(size_t)OUT * EMB];
__device__ float    d_wt[8 * EMB];                       // folded att vectors
__device__ float    d_asrc[N_NODES * HEADS];
__device__ float    d_adst[N_NODES * HEADS];
__device__ float    d_alpha[(size_t)NTOT * HEADS];
__device__ unsigned d_amax[N_NODES * HEADS];
__device__ float    d_denom[N_NODES * HEADS];
__device__ int      d_deg[N_NODES];
__device__ int      d_off[N_NODES + 1];
__device__ int      d_pos[N_NODES];
__device__ int      d_eidx[NTOT];
__device__ int      d_bsum[32];
__device__ int      d_boff[32];
__device__ int      d_gcnt[NB];
__device__ float    d_gsum[NB * OUT];
__device__ unsigned d_gmaxE[NB * OUT];
__device__ float    d_g[NB * 2 * OUT];

__device__ __forceinline__ unsigned fenc(float f) {
    unsigned u = __float_as_uint(f);
    return (u >> 31) ? ~u : (u | 0x80000000u);
}
__device__ __forceinline__ float fdec(unsigned u) {
    u = (u >> 31) ? (u & 0x7fffffffu) : ~u;
    return __uint_as_float(u);
}
__device__ __forceinline__ void dec2(float v, __nv_bfloat16& h, __nv_bfloat16& l) {
    h = __float2bfloat16_rn(v);
    l = __float2bfloat16_rn(v - __bfloat162float(h));
}
__device__ __forceinline__ void mma16816(float* c, const unsigned* a, const unsigned* b) {
    asm volatile(
        "mma.sync.aligned.m16n8k16.row.col.f32.bf16.bf16.f32 "
        "{%0,%1,%2,%3}, {%4,%5,%6,%7}, {%8,%9}, {%0,%1,%2,%3};"
        : "+f"(c[0]), "+f"(c[1]), "+f"(c[2]), "+f"(c[3])
        : "r"(a[0]), "r"(a[1]), "r"(a[2]), "r"(a[3]), "r"(b[0]), "r"(b[1]));
}
__device__ __forceinline__ void ldsm_x4(unsigned* r, unsigned addr) {
    asm volatile("ldmatrix.sync.aligned.m8n8.x4.shared.b16 {%0,%1,%2,%3}, [%4];"
                 : "=r"(r[0]), "=r"(r[1]), "=r"(r[2]), "=r"(r[3]) : "r"(addr));
}
__device__ __forceinline__ void cpasync16(unsigned saddr, const void* gaddr) {
    asm volatile("cp.async.cg.shared.global [%0], [%1], 16;" :: "r"(saddr), "l"(gaddr));
}
__device__ __forceinline__ void cpcommit() { asm volatile("cp.async.commit_group;"); }
__device__ __forceinline__ void cpwaitall() { asm volatile("cp.async.wait_group 0;"); }

// ---------------- init ------------------------------------------------------
__global__ void init_kernel() {
    int i = blockIdx.x * blockDim.x + threadIdx.x;   // 131072 threads
    if (i < N_NODES * HEADS) { d_amax[i] = 0u; d_denom[i] = 0.f; }
    if (i < N_NODES) d_deg[i] = 0;
    if (i < NB * OUT) { d_gsum[i] = 0.f; d_gmaxE[i] = fenc(-INFINITY); }
    if (i < NB) d_gcnt[i] = 0;
}

// ---------------- weight prep: transpose fp32 [K][N] -> bf16 hi/lo [N][K] ---
__global__ void prepW_kernel(const float* __restrict__ W, int K, int N,
                             __nv_bfloat16* __restrict__ Whi,
                             __nv_bfloat16* __restrict__ Wlo) {
    __shared__ float tile[32][33];
    int kx = blockIdx.y * 32, nx = blockIdx.x * 32;
    int tx = threadIdx.x & 31, ty = threadIdx.x >> 5;
#pragma unroll
    for (int p = 0; p < 4; p++)
        tile[ty + p * 8][tx] = W[(long)(kx + ty + p * 8) * N + nx + tx];
    __syncthreads();
#pragma unroll
    for (int p = 0; p < 4; p++) {
        int nl = ty + p * 8, kl = tx;
        float v = tile[kl][nl];
        __nv_bfloat16 h, l;
        dec2(v, h, l);
        long o = (long)(nx + nl) * K + kx + kl;
        Whi[o] = h;
        Wlo[o] = l;
    }
}

// ---------------- fold att vectors through W_gat ----------------------------
__global__ void prepwt_kernel(const float* __restrict__ W_gat,
                              const float* __restrict__ att_src,
                              const float* __restrict__ att_dst) {
    int k = blockIdx.x;
    int w = threadIdx.x >> 5, lane = threadIdx.x & 31;
    int hd = w & 3;
    const float* att = (w < 4) ? att_src : att_dst;
    const float* wr = W_gat + (long)k * OUT + hd * EMB;
    const float* ar = att + hd * EMB;
    float s = 0.f;
    for (int c = lane; c < EMB; c += 32) s += wr[c] * ar[c];
#pragma unroll
    for (int o = 16; o; o >>= 1) s += __shfl_down_sync(0xffffffffu, s, o);
    if (lane == 0) d_wt[w * EMB + k] = s;
}

// ---------------- gather emb rows + decompose to bf16 hi/lo -----------------
__global__ void gathdec_kernel(const float* __restrict__ emb,
                               const int* __restrict__ code) {
    long i = (long)blockIdx.x * blockDim.x + threadIdx.x;
    int row = (int)(i >> 7);
    int c4 = (int)(i & 127) * 4;
    float4 v = *(const float4*)(emb + (long)code[row] * EMB + c4);
    __nv_bfloat16 h0, l0, h1, l1, h2, l2, h3, l3;
    dec2(v.x, h0, l0); dec2(v.y, h1, l1);
    dec2(v.z, h2, l2); dec2(v.w, h3, l3);
    long o = (long)row * EMB + c4;
    __nv_bfloat162 p;
    p.x = h0; p.y = h1; *(__nv_bfloat162*)&d_xehi[o] = p;
    p.x = h2; p.y = h3; *(__nv_bfloat162*)&d_xehi[o + 2] = p;
    p.x = l0; p.y = l1; *(__nv_bfloat162*)&d_xelo[o] = p;
    p.x = l2; p.y = l3; *(__nv_bfloat162*)&d_xelo[o + 2] = p;
}

// ---------------- bf16x3 tensor-core GEMM (cp.async + ldmatrix) -------------
// POOL=false: C[r][c] = sum_k A[r][k]*B[c][k] + bias[c] (fp32 out).
// POOL=true: v = leaky_0.01(acc+bias); segment mean/max pooled by batch[row]
//            into d_gsum / d_gmaxE (no C written).
template <bool POOL>
__global__ void __launch_bounds__(256, 2) gemm_fast_kernel(
    const __nv_bfloat16* __restrict__ Ahi, const __nv_bfloat16* __restrict__ Alo,
    int lda,
    const __nv_bfloat16* __restrict__ Bhi, const __nv_bfloat16* __restrict__ Blo,
    const float* __restrict__ bias,
    float* __restrict__ C, int ldc,
    int K, long zsA, long zsB, int zsBias,
    const int* __restrict__ batch) {
    extern __shared__ char smem[];
    unsigned sbase = (unsigned)__cvta_generic_to_shared(smem);

    int hz = blockIdx.z;
    Ahi += (long)hz * zsA; Alo += (long)hz * zsA;
    Bhi += (long)hz * zsB; Blo += (long)hz * zsB;
    bias += hz * zsBias;

    int tid = threadIdx.x;
    int wid = tid >> 5, lane = tid & 31;
    int warp_m = wid >> 1, warp_n = wid & 1;
    int brow = blockIdx.y * BM, bcol = blockIdx.x * BN;

    const __nv_bfloat16 *agp_h[4], *agp_l[4], *bgp_h[2], *bgp_l[2];
    unsigned asm_h[4], asm_l[4], bsm_h[2], bsm_l[2];
#pragma unroll
    for (int p = 0; p < 4; p++) {
        int id = tid + 256 * p;
        int ar = id >> 3, ac = id & 7;
        agp_h[p] = Ahi + (long)(brow + ar) * lda + ac * 8;
        agp_l[p] = Alo + (long)(brow + ar) * lda + ac * 8;
        unsigned so = ar * 128 + ((ac ^ (ar & 7)) << 4);
        asm_h[p] = so;
        asm_l[p] = 16384 + so;
    }
#pragma unroll
    for (int p = 0; p < 2; p++) {
        int id = tid + 256 * p;
        int br = id >> 3, bc = id & 7;
        bgp_h[p] = Bhi + (long)(bcol + br) * K + bc * 8;
        bgp_l[p] = Blo + (long)(bcol + br) * K + bc * 8;
        unsigned so = br * 128 + ((bc ^ (br & 7)) << 4);
        bsm_h[p] = 32768 + so;
        bsm_l[p] = 40960 + so;
    }

    float acc[2][4][4];
#pragma unroll
    for (int mi = 0; mi < 2; mi++)
#pragma unroll
        for (int ni = 0; ni < 4; ni++)
#pragma unroll
            for (int j = 0; j < 4; j++) acc[mi][ni][j] = 0.f;

    int nch = K / BKC;
    {
        unsigned sb = sbase;
#pragma unroll
        for (int p = 0; p < 4; p++) {
            cpasync16(sb + asm_h[p], agp_h[p]);
            cpasync16(sb + asm_l[p], agp_l[p]);
        }
#pragma unroll
        for (int p = 0; p < 2; p++) {
            cpasync16(sb + bsm_h[p], bgp_h[p]);
            cpasync16(sb + bsm_l[p], bgp_l[p]);
        }
        cpcommit();
    }

    int a_lrow = (lane & 15);
    int a_lchsel = (lane >> 4);
    int b_lrow = (lane & 7) + ((lane >> 4) << 3);
    int b_lchsel = (lane >> 3) & 1;

    for (int ch = 0; ch < nch; ch++) {
        cpwaitall();
        __syncthreads();
        unsigned cur = sbase + (unsigned)(ch & 1) * GEMM_STAGE_BYTES;
        if (ch + 1 < nch) {
            unsigned nxt = sbase + (unsigned)((ch + 1) & 1) * GEMM_STAGE_BYTES;
            int kk = (ch + 1) * BKC;
#pragma unroll
            for (int p = 0; p < 4; p++) {
                cpasync16(nxt + asm_h[p], agp_h[p] + kk);
                cpasync16(nxt + asm_l[p], agp_l[p] + kk);
            }
#pragma unroll
            for (int p = 0; p < 2; p++) {
                cpasync16(nxt + bsm_h[p], bgp_h[p] + kk);
                cpasync16(nxt + bsm_l[p], bgp_l[p] + kk);
            }
            cpcommit();
        }

#pragma unroll
        for (int ks = 0; ks < 4; ks++) {
            int cb = ks << 1;
            unsigned ah[2][4], al_[2][4];
#pragma unroll
            for (int mi = 0; mi < 2; mi++) {
                int row = warp_m * 32 + mi * 16 + a_lrow;
                int c = cb + a_lchsel;
                unsigned off = row * 128 + (((unsigned)(c ^ (row & 7))) << 4);
                ldsm_x4(ah[mi], cur + off);
                ldsm_x4(al_[mi], cur + 16384 + off);
            }
            unsigned bh[4][2], bl[4][2];
#pragma unroll
            for (int p = 0; p < 2; p++) {
                int row = warp_n * 32 + p * 16 + b_lrow;
                int c = cb + b_lchsel;
                unsigned off = row * 128 + (((unsigned)(c ^ (row & 7))) << 4);
                unsigned r4[4];
                ldsm_x4(r4, cur + 32768 + off);
                bh[2 * p][0] = r4[0]; bh[2 * p][1] = r4[1];
                bh[2 * p + 1][0] = r4[2]; bh[2 * p + 1][1] = r4[3];
                ldsm_x4(r4, cur + 40960 + off);
                bl[2 * p][0] = r4[0]; bl[2 * p][1] = r4[1];
                bl[2 * p + 1][0] = r4[2]; bl[2 * p + 1][1] = r4[3];
            }
#pragma unroll
            for (int mi = 0; mi < 2; mi++)
#pragma unroll
                for (int ni = 0; ni < 4; ni++) {
                    mma16816(acc[mi][ni], ah[mi], bl[ni]);
                    mma16816(acc[mi][ni], al_[mi], bh[ni]);
                    mma16816(acc[mi][ni], ah[mi], bh[ni]);
                }
        }
        __syncthreads();
    }

    int g = lane >> 2, t = lane & 3;
    if (!POOL) {
#pragma unroll
        for (int mi = 0; mi < 2; mi++) {
            int r0 = brow + warp_m * 32 + mi * 16 + g;
#pragma unroll
            for (int ni = 0; ni < 4; ni++) {
                int c0 = bcol + warp_n * 32 + ni * 8 + 2 * t;
                float b0 = bias[c0], b1 = bias[c0 + 1];
                *(float2*)&C[(long)r0 * ldc + c0] =
                    make_float2(acc[mi][ni][0] + b0, acc[mi][ni][1] + b1);
                *(float2*)&C[(long)(r0 + 8) * ldc + c0] =
                    make_float2(acc[mi][ni][2] + b0, acc[mi][ni][3] + b1);
            }
        }
    } else {
        // stage leaky(acc+bias) in smem, then segment mean/max pool by batch id
        float* sp = (float*)smem;            // [128][65]
        int* sb = (int*)(smem + 128 * 65 * 4);  // [128]
#pragma unroll
        for (int mi = 0; mi < 2; mi++) {
            int rl = warp_m * 32 + mi * 16 + g;
#pragma unroll
            for (int ni = 0; ni < 4; ni++) {
                int cl = warp_n * 32 + ni * 8 + 2 * t;
                float b0 = bias[bcol + cl], b1 = bias[bcol + cl + 1];
                float v0 = acc[mi][ni][0] + b0;
                float v1 = acc[mi][ni][1] + b1;
                float v2 = acc[mi][ni][2] + b0;
                float v3 = acc[mi][ni][3] + b1;
                v0 = v0 > 0.f ? v0 : 0.01f * v0;
                v1 = v1 > 0.f ? v1 : 0.01f * v1;
                v2 = v2 > 0.f ? v2 : 0.01f * v2;
                v3 = v3 > 0.f ? v3 : 0.01f * v3;
                sp[rl * 65 + cl] = v0;
                sp[rl * 65 + cl + 1] = v1;
                sp[(rl + 8) * 65 + cl] = v2;
                sp[(rl + 8) * 65 + cl + 1] = v3;
            }
        }
        if (tid < 128) sb[tid] = batch[brow + tid];
        __syncthreads();
        if (tid < BN) {
            int gcol = hz * EMB + bcol + tid;
            int curg = sb[0];
            float s = 0.f, m = -INFINITY;
            for (int r = 0; r < BM; r++) {
                int gg = sb[r];
                if (gg != curg) {
                    atomicAdd(&d_gsum[curg * OUT + gcol], s);
                    atomicMax(&d_gmaxE[curg * OUT + gcol], fenc(m));
                    s = 0.f; m = -INFINITY; curg = gg;
                }
                float v = sp[r * 65 + tid];
                s += v;
                m = fmaxf(m, v);
            }
            atomicAdd(&d_gsum[curg * OUT + gcol], s);
            atomicMax(&d_gmaxE[curg * OUT + gcol], fenc(m));
        }
    }
}

// ---------------- attention scalars from x and folded wt --------------------
__global__ void attnx_kernel() {
    __shared__ float wt[8 * EMB];
    int tid = threadIdx.x;  // 256
    for (int i = tid; i < 8 * EMB; i += 256) wt[i] = d_wt[i];
    __syncthreads();
    int w = tid >> 5, lane = tid & 31;
    int n = blockIdx.x * 8 + w;
    const float* xr = d_x + (size_t)n * EMB;
    float s[8] = {0.f, 0.f, 0.f, 0.f, 0.f, 0.f, 0.f, 0.f};
#pragma unroll
    for (int i = 0; i < EMB / 32; i++) {
        float xv = xr[lane + 32 * i];
#pragma unroll
        for (int q = 0; q < 8; q++) s[q] += xv * wt[q * EMB + lane + 32 * i];
    }
#pragma unroll
    for (int o = 16; o; o >>= 1)
#pragma unroll
        for (int q = 0; q < 8; q++) s[q] += __shfl_down_sync(0xffffffffu, s[q], o);
    if (lane == 0) {
        *(float4*)&d_asrc[n * 4] = make_float4(s[0], s[1], s[2], s[3]);
        *(float4*)&d_adst[n * 4] = make_float4(s[4], s[5], s[6], s[7]);
    }
}

// ---------------- pass 1 over edges: deg count + raw alpha + amax -----------
__global__ void countalpha_kernel(const int* __restrict__ ei) {
    int e = blockIdx.x * blockDim.x + threadIdx.x;
    if (e >= NTOT) return;
    int src, dst;
    if (e < NE) { src = ei[e]; dst = ei[NE + e]; }
    else        { src = dst = e - NE; }
    atomicAdd(&d_deg[dst], 1);
    float4 as = *(const float4*)&d_asrc[src * 4];
    float4 ad = *(const float4*)&d_adst[dst * 4];
    float r[4] = {as.x + ad.x, as.y + ad.y, as.z + ad.z, as.w + ad.w};
#pragma unroll
    for (int h = 0; h < 4; h++) {
        r[h] = r[h] > 0.f ? r[h] : 0.2f * r[h];
        atomicMax(&d_amax[dst * 4 + h], fenc(r[h]));
    }
    *(float4*)&d_alpha[(size_t)e * 4] = make_float4(r[0], r[1], r[2], r[3]);
}

// ---------------- fast scan (3 kernels) -------------------------------------
__global__ void scanA_kernel() {  // grid 32, block 1024
    int b = blockIdx.x, tid = threadIdx.x;
    int i = b * 1024 + tid;
    int v = d_deg[i];
    int lane = tid & 31, w = tid >> 5;
    int x = v;
#pragma unroll
    for (int o = 1; o < 32; o <<= 1) {
        int y = __shfl_up_sync(0xffffffffu, x, o);
        if (lane >= o) x += y;
    }
    __shared__ int ws[32];
    if (lane == 31) ws[w] = x;
    __syncthreads();
    if (w == 0) {
        int z = ws[lane];
#pragma unroll
        for (int o = 1; o < 32; o <<= 1) {
            int y = __shfl_up_sync(0xffffffffu, z, o);
            if (lane >= o) z += y;
        }
        ws[lane] = z;
    }
    __syncthreads();
    int incl = x + (w ? ws[w - 1] : 0);
    d_off[i] = incl - v;
    if (tid == 1023) d_bsum[b] = incl;
}

__global__ void scanB_kernel() {  // 1 block, 32 threads
    int lane = threadIdx.x;
    int v = d_bsum[lane];
    int x = v;
#pragma unroll
    for (int o = 1; o < 32; o <<= 1) {
        int y = __shfl_up_sync(0xffffffffu, x, o);
        if (lane >= o) x += y;
    }
    d_boff[lane] = x - v;
    if (lane == 31) d_off[N_NODES] = x;
}

__global__ void scanC_kernel(const int* __restrict__ batch) {  // grid 32, 1024
    int b = blockIdx.x, tid = threadIdx.x;
    int i = b * 1024 + tid;
    int o = d_off[i] + d_boff[b];
    d_off[i] = o;
    d_pos[i] = o;
    atomicAdd(&d_gcnt[batch[i]], 1);
}

// ---------------- pass 2 over edges: softmax finalize + CSR scatter ---------
__global__ void alpha2scatter_kernel(const int* __restrict__ ei) {
    int e = blockIdx.x * blockDim.x + threadIdx.x;
    if (e >= NTOT) return;
    int dst = (e < NE) ? ei[NE + e] : (e - NE);
    float4 r = *(const float4*)&d_alpha[(size_t)e * 4];
    float a0 = expf(r.x - fdec(d_amax[dst * 4 + 0]));
    float a1 = expf(r.y - fdec(d_amax[dst * 4 + 1]));
    float a2 = expf(r.z - fdec(d_amax[dst * 4 + 2]));
    float a3 = expf(r.w - fdec(d_amax[dst * 4 + 3]));
    *(float4*)&d_alpha[(size_t)e * 4] = make_float4(a0, a1, a2, a3);
    atomicAdd(&d_denom[dst * 4 + 0], a0);
    atomicAdd(&d_denom[dst * 4 + 1], a1);
    atomicAdd(&d_denom[dst * 4 + 2], a2);
    atomicAdd(&d_denom[dst * 4 + 3], a3);
    int p = atomicAdd(&d_pos[dst], 1);
    d_eidx[p] = e;
}

// ---------------- aggregation in x-space ------------------------------------
__global__ void aggregate_kernel(const int* __restrict__ ei) {
    int dst = blockIdx.x, t = threadIdx.x;  // 256 threads, 2 channels each
    int c = t * 2;
    float acc[4][2] = {{0.f, 0.f}, {0.f, 0.f}, {0.f, 0.f}, {0.f, 0.f}};
    int s = d_off[dst], e = d_off[dst + 1];
    float4 dn = *(const float4*)&d_denom[dst * 4];
    float inv0 = 1.f / (dn.x + 1e-16f);
    float inv1 = 1.f / (dn.y + 1e-16f);
    float inv2 = 1.f / (dn.z + 1e-16f);
    float inv3 = 1.f / (dn.w + 1e-16f);
    for (int i = s; i < e; i++) {
        int ed = d_eidx[i];
        int src = (ed < NE) ? ei[ed] : (ed - NE);
        float4 al = *(const float4*)&d_alpha[(size_t)ed * 4];
        float a0 = al.x * inv0, a1 = al.y * inv1, a2 = al.z * inv2, a3 = al.w * inv3;
        float2 xv = *(const float2*)(d_x + (size_t)src * EMB + c);
        acc[0][0] += a0 * xv.x; acc[0][1] += a0 * xv.y;
        acc[1][0] += a1 * xv.x; acc[1][1] += a1 * xv.y;
        acc[2][0] += a2 * xv.x; acc[2][1] += a2 * xv.y;
        acc[3][0] += a3 * xv.x; acc[3][1] += a3 * xv.y;
    }
#pragma unroll
    for (int hd = 0; hd < 4; hd++) {
        __nv_bfloat16 h0, l0, h1, l1;
        dec2(acc[hd][0], h0, l0);
        dec2(acc[hd][1], h1, l1);
        size_t o = ((size_t)dst * 4 + hd) * EMB + c;
        __nv_bfloat162 hp, lp;
        hp.x = h0; hp.y = h1; lp.x = l0; lp.y = l1;
        *(__nv_bfloat162*)&d_zhi[o] = hp;
        *(__nv_bfloat162*)&d_zlo[o] = lp;
    }
}

// ---------------- finalize pooled features ----------------------------------
__global__ void gfinal_kernel() {
    int i = blockIdx.x * blockDim.x + threadIdx.x;  // NB*OUT
    int b = i >> 11, c = i & (OUT - 1);
    float cnt = (float)d_gcnt[b];
    d_g[b * 2 * OUT + c] = d_gsum[i] / fmaxf(cnt, 1.f);
    d_g[b * 2 * OUT + OUT + c] = fdec(d_gmaxE[i]);
}

// ---------------- head MLPs -------------------------------------------------
__global__ void mlp_kernel(const float* __restrict__ W1r, const float* __restrict__ b1r,
                           const float* __restrict__ W2r, const float* __restrict__ b2r,
                           const float* __restrict__ W1m, const float* __restrict__ b1m,
                           const float* __restrict__ W2m, const float* __restrict__ b2m,
                           float* __restrict__ out) {
    int b = blockIdx.x, task = blockIdx.y;
    const float* W1 = task ? W1m : W1r;
    const float* b1 = task ? b1m : b1r;
    const float* W2 = task ? W2m : W2r;
    const float* b2 = task ? b2m : b2r;
    __shared__ float gs[2 * OUT];
    __shared__ float part[128];
    int t = threadIdx.x;
    for (int k = t; k < 2 * OUT; k += 128) gs[k] = d_g[b * 2 * OUT + k];
    __syncthreads();
    int j = t & 31, seg = t >> 5;
    float s = 0.f;
    for (int k = seg; k < 2 * OUT; k += 4) s += gs[k] * W1[k * HID + j];
    part[t] = s;
    __syncthreads();
    if (t < 32) {
        float hj = part[t] + part[t + 32] + part[t + 64] + part[t + 96] + b1[t];
        hj = fmaxf(hj, 0.f);
        float p = hj * W2[t];
#pragma unroll
        for (int o = 16; o; o >>= 1) p += __shfl_down_sync(0xffffffffu, p, o);
        if (t == 0) out[task * NB + b] = p + b2[0];
    }
}

// ---------------- launch ----------------------------------------------------
extern "C" void kernel_launch(void* const* d_in, const int* in_sizes, int n_in,
                              void* d_out, int out_size) {
    const int*   code     = (const int*)d_in[0];
    const int*   ei       = (const int*)d_in[1];
    const int*   batch    = (const int*)d_in[2];
    const float* emb      = (const float*)d_in[3];
    const float* W_feat   = (const float*)d_in[4];
    const float* b_feat   = (const float*)d_in[5];
    const float* W_gat    = (const float*)d_in[6];
    const float* att_src  = (const float*)d_in[7];
    const float* att_dst  = (const float*)d_in[8];
    const float* bias_gat = (const float*)d_in[9];
    const float* W1r = (const float*)d_in[10];
    const float* b1r = (const float*)d_in[11];
    const float* W2r = (const float*)d_in[12];
    const float* b2r = (const float*)d_in[13];
    const float* W1m = (const float*)d_in[14];
    const float* b1m = (const float*)d_in[15];
    const float* W2m = (const float*)d_in[16];
    const float* b2m = (const float*)d_in[17];
    float* out = (float*)d_out;

    static int attr_done = 0;
    if (!attr_done) {
        cudaFuncSetAttribute(gemm_fast_kernel<false>,
                             cudaFuncAttributeMaxDynamicSharedMemorySize, GEMM_SMEM);
        cudaFuncSetAttribute(gemm_fast_kernel<true>,
                             cudaFuncAttributeMaxDynamicSharedMemorySize, GEMM_SMEM);
        attr_done = 1;
    }

    void *p0, *p1, *p2, *p3, *p4, *p6, *p7, *p8, *p9;
    cudaGetSymbolAddress(&p0, d_xehi);
    cudaGetSymbolAddress(&p1, d_xelo);
    cudaGetSymbolAddress(&p2, d_x);
    cudaGetSymbolAddress(&p3, d_zhi);
    cudaGetSymbolAddress(&p4, d_zlo);
    cudaGetSymbolAddress(&p6, d_wfhi);
    cudaGetSymbolAddress(&p7, d_wflo);
    cudaGetSymbolAddress(&p8, d_wghi);
    cudaGetSymbolAddress(&p9, d_wglo);
    __nv_bfloat16* xehi = (__nv_bfloat16*)p0;
    __nv_bfloat16* xelo = (__nv_bfloat16*)p1;
    float*         xp   = (float*)p2;
    __nv_bfloat16* zhi  = (__nv_bfloat16*)p3;
    __nv_bfloat16* zlo  = (__nv_bfloat16*)p4;
    __nv_bfloat16* wfhi = (__nv_bfloat16*)p6;
    __nv_bfloat16* wflo = (__nv_bfloat16*)p7;
    __nv_bfloat16* wghi = (__nv_bfloat16*)p8;
    __nv_bfloat16* wglo = (__nv_bfloat16*)p9;

    init_kernel<<<(N_NODES * HEADS + 255) / 256, 256>>>();

    prepW_kernel<<<dim3(EMB / 32, EMB / 32), 256>>>(W_feat, EMB, EMB, wfhi, wflo);
    prepW_kernel<<<dim3(OUT / 32, EMB / 32), 256>>>(W_gat, EMB, OUT, wghi, wglo);
    prepwt_kernel<<<EMB, 256>>>(W_gat, att_src, att_dst);
    gathdec_kernel<<<(N_NODES * EMB / 4) / 256, 256>>>(emb, code);

    // x = emb[code] @ W_feat + b_feat  -> fp32
    gemm_fast_kernel<false><<<dim3(EMB / BN, N_NODES / BM, 1), 256, GEMM_SMEM>>>(
        xehi, xelo, EMB, wfhi, wflo, b_feat, xp, EMB, EMB, 0, 0, 0, nullptr);

    attnx_kernel<<<N_NODES / 8, 256>>>();

    countalpha_kernel<<<(NTOT + 255) / 256, 256>>>(ei);
    scanA_kernel<<<32, 1024>>>();
    scanB_kernel<<<1, 32>>>();
    scanC_kernel<<<32, 1024>>>(batch);
    alpha2scatter_kernel<<<(NTOT + 255) / 256, 256>>>(ei);

    aggregate_kernel<<<N_NODES, 256>>>(ei);

    // z @ Wg per head, bias + leaky + segment mean/max pooling fused
    gemm_fast_kernel<true><<<dim3(EMB / BN, N_NODES / BM, HEADS), 256, GEMM_SMEM>>>(
        zhi, zlo, OUT, wghi, wglo, bias_gat, nullptr, 0,
        EMB, (long)EMB, (long)EMB * EMB, EMB, batch);

    gfinal_kernel<<<(NB * OUT) / 256, 256>>>();

    mlp_kernel<<<dim3(NB, 2), 128>>>(W1r, b1r, W2r, b2r, W1m, b1m, W2m, b2m, out);
}